// round 1
// baseline (speedup 1.0000x reference)
#include <cuda_runtime.h>
#include <math.h>

// Problem constants
constexpr int BB = 4;
constexpr int SS = 2048;
constexpr int DD = 1024;
constexpr int FF = 4096;
constexpr int MM = BB * SS;              // 8192 rows
constexpr long long BSD = (long long)MM * DD;  // 8,388,608

// ---------------- scratch (static device globals; no allocation) ------------
__device__ float g_xnorm [MM * DD];
__device__ float g_gatepre[MM * DD];
__device__ float g_apre  [MM * DD];
__device__ float g_a     [MM * DD];
__device__ float g_u     [MM * DD];
__device__ float g_concat[MM * 2 * DD];   // [conv | griffin_h]
__device__ float g_xnew  [MM * DD];
__device__ float g_normed[MM * DD];
__device__ float g_hidden[MM * FF];
__device__ float g_splam [DD];

// ---------------- rmsnorm: one block per row, 256 threads x float4 ----------
__global__ void rmsnorm_kernel(const float* __restrict__ in,
                               const float* __restrict__ w,
                               float* __restrict__ out) {
    int row = blockIdx.x;
    const float4* ip = (const float4*)(in + (size_t)row * DD);
    float4 v = ip[threadIdx.x];
    float ss = v.x*v.x + v.y*v.y + v.z*v.z + v.w*v.w;
    #pragma unroll
    for (int o = 16; o > 0; o >>= 1) ss += __shfl_xor_sync(0xffffffffu, ss, o);
    __shared__ float ws[8];
    int lane = threadIdx.x & 31, wid = threadIdx.x >> 5;
    if (lane == 0) ws[wid] = ss;
    __syncthreads();
    if (wid == 0) {
        float s = (lane < 8) ? ws[lane] : 0.f;
        #pragma unroll
        for (int o = 4; o > 0; o >>= 1) s += __shfl_xor_sync(0xffffffffu, s, o);
        if (lane == 0) ws[0] = s;
    }
    __syncthreads();
    float rms = rsqrtf(ws[0] * (1.0f / DD) + 1e-6f);
    float4 wv = ((const float4*)w)[threadIdx.x];
    float4 o;
    o.x = v.x * rms * wv.x;
    o.y = v.y * rms * wv.y;
    o.z = v.z * rms * wv.z;
    o.w = v.w * rms * wv.w;
    ((float4*)(out + (size_t)row * DD))[threadIdx.x] = o;
}

// ---------------- splam[d] = 8 * softplus(lam[d]) ---------------------------
__global__ void splam_kernel(const float* __restrict__ lam) {
    int d = blockIdx.x * blockDim.x + threadIdx.x;
    if (d < DD) {
        float l = lam[d];
        float sp = (l > 20.f) ? l : log1pf(expf(l));
        g_splam[d] = 8.0f * sp;
    }
}

// ------- fused: depthwise causal conv (into concat[:, :D]) + a/u gating -----
__global__ void gating_conv_kernel(const float* __restrict__ ck,
                                   const float* __restrict__ cb) {
    long long i = (long long)blockIdx.x * blockDim.x + threadIdx.x;  // < BSD
    int d = (int)(i & (DD - 1));
    long long r = i >> 10;               // row = b*S + t
    int t = (int)(r & (SS - 1));
    float xn = g_xnorm[i];
    float4 kv = ((const float4*)ck)[d];  // conv_kernel[d][0..3]
    float conv = cb[d] + kv.x * xn;
    if (t >= 1) conv += kv.y * g_xnorm[i - DD];
    if (t >= 2) conv += kv.z * g_xnorm[i - 2 * DD];
    if (t >= 3) conv += kv.w * g_xnorm[i - 3 * DD];
    float gate = 1.f / (1.f + expf(-g_gatepre[i]));
    float sa   = 1.f / (1.f + expf(-g_apre[i]));
    float a = expf(-g_splam[d] * sa);
    float u = sqrtf(fmaxf(1.f - a * a, 0.f)) * gate * xn;
    g_concat[r * (2 * DD) + d] = conv;
    g_a[i] = a;
    g_u[i] = u;
}

// ---------------- RG-LRU sequential scan, one thread per (b,d) channel ------
__global__ void scan_kernel() {
    int c = blockIdx.x * blockDim.x + threadIdx.x;  // < B*D
    int b = c >> 10;
    int d = c & (DD - 1);
    long long base = (long long)b * SS * DD + d;
    long long crow = (long long)b * SS * (2 * DD) + DD + d;
    float h = 0.f;
    #pragma unroll 4
    for (int t = 0; t < SS; t++) {
        long long idx = base + (long long)t * DD;
        h = fmaf(g_a[idx], h, g_u[idx]);
        g_concat[crow] = h;
        crow += 2 * DD;
    }
}

// ---------------- SGEMM: 128x128x16 tiles, 8x8 microtile, fused epilogues ---
// EPI: 0 = plain store
//      1 = mixer:  vel = sigmoid(log_beta)*aux1 + (acc+bias); C=vel; out2=aux2+vel
//      2 = gelu(acc + bias)  (tanh approximation, JAX default)
//      3 = acc + bias + aux1 (final residual)
template <int EPI>
__global__ void __launch_bounds__(256, 2)
sgemm_kernel(const float* __restrict__ A, const float* __restrict__ Bmat,
             float* __restrict__ C, int M, int N, int K,
             const float* __restrict__ bias,
             const float* __restrict__ aux1,   // velocity (1) / xnew (3)
             const float* __restrict__ aux2,   // x (1)
             const float* __restrict__ aux3,   // log_beta (1)
             float* __restrict__ out2) {       // xnew out (1)
    __shared__ float As[16][132];
    __shared__ float Bs[16][132];
    int tid = threadIdx.x;
    int bm = blockIdx.x, bn = blockIdx.y;
    int ty = tid >> 4, tx = tid & 15;

    float acc[8][8];
    #pragma unroll
    for (int i = 0; i < 8; i++)
        #pragma unroll
        for (int j = 0; j < 8; j++) acc[i][j] = 0.f;

    const float* Ab = A + (size_t)bm * 128 * K;
    const float* Bb = Bmat + (size_t)bn * 128;

    for (int k0 = 0; k0 < K; k0 += 16) {
        // load A tile (128x16), store transposed
        #pragma unroll
        for (int i = 0; i < 2; i++) {
            int idx = tid + i * 256;
            int ar = idx >> 2, ac4 = idx & 3;
            float4 v = *(const float4*)(Ab + (size_t)ar * K + k0 + ac4 * 4);
            As[ac4 * 4 + 0][ar] = v.x;
            As[ac4 * 4 + 1][ar] = v.y;
            As[ac4 * 4 + 2][ar] = v.z;
            As[ac4 * 4 + 3][ar] = v.w;
        }
        // load B tile (16x128)
        #pragma unroll
        for (int i = 0; i < 2; i++) {
            int idx = tid + i * 256;
            int br = idx >> 5, bc4 = idx & 31;
            float4 v = *(const float4*)(Bb + (size_t)(k0 + br) * N + bc4 * 4);
            *(float4*)&Bs[br][bc4 * 4] = v;
        }
        __syncthreads();
        #pragma unroll
        for (int k = 0; k < 16; k++) {
            float4 a0 = *(const float4*)&As[k][ty * 4];
            float4 a1 = *(const float4*)&As[k][64 + ty * 4];
            float4 b0 = *(const float4*)&Bs[k][tx * 4];
            float4 b1 = *(const float4*)&Bs[k][64 + tx * 4];
            float av[8] = {a0.x, a0.y, a0.z, a0.w, a1.x, a1.y, a1.z, a1.w};
            float bv[8] = {b0.x, b0.y, b0.z, b0.w, b1.x, b1.y, b1.z, b1.w};
            #pragma unroll
            for (int i = 0; i < 8; i++)
                #pragma unroll
                for (int j = 0; j < 8; j++)
                    acc[i][j] = fmaf(av[i], bv[j], acc[i][j]);
        }
        __syncthreads();
    }

    // vectorized epilogue (cols tx*4.. are contiguous per half)
    #pragma unroll
    for (int i = 0; i < 8; i++) {
        int row = bm * 128 + ty * 4 + (i & 3) + ((i & 4) ? 64 : 0);
        #pragma unroll
        for (int jh = 0; jh < 2; jh++) {
            int col = bn * 128 + tx * 4 + jh * 64;
            size_t off = (size_t)row * N + col;
            float4 v = make_float4(acc[i][jh * 4 + 0], acc[i][jh * 4 + 1],
                                   acc[i][jh * 4 + 2], acc[i][jh * 4 + 3]);
            if (EPI == 0) {
                *(float4*)(C + off) = v;
            } else if (EPI == 1) {
                float4 bia = *(const float4*)(bias + col);
                float4 lb  = *(const float4*)(aux3 + col);
                float4 vel = *(const float4*)(aux1 + off);
                float4 xv  = *(const float4*)(aux2 + off);
                float4 vn;
                vn.x = fmaf(1.f / (1.f + __expf(-lb.x)), vel.x, v.x + bia.x);
                vn.y = fmaf(1.f / (1.f + __expf(-lb.y)), vel.y, v.y + bia.y);
                vn.z = fmaf(1.f / (1.f + __expf(-lb.z)), vel.z, v.z + bia.z);
                vn.w = fmaf(1.f / (1.f + __expf(-lb.w)), vel.w, v.w + bia.w);
                *(float4*)(C + off) = vn;
                float4 xn;
                xn.x = xv.x + vn.x; xn.y = xv.y + vn.y;
                xn.z = xv.z + vn.z; xn.w = xv.w + vn.w;
                *(float4*)(out2 + off) = xn;
            } else if (EPI == 2) {
                float4 bia = *(const float4*)(bias + col);
                float t0 = v.x + bia.x, t1 = v.y + bia.y, t2 = v.z + bia.z, t3 = v.w + bia.w;
                const float c0 = 0.7978845608028654f, c1 = 0.044715f;
                float4 o;
                o.x = 0.5f * t0 * (1.f + tanhf(c0 * (t0 + c1 * t0 * t0 * t0)));
                o.y = 0.5f * t1 * (1.f + tanhf(c0 * (t1 + c1 * t1 * t1 * t1)));
                o.z = 0.5f * t2 * (1.f + tanhf(c0 * (t2 + c1 * t2 * t2 * t2)));
                o.w = 0.5f * t3 * (1.f + tanhf(c0 * (t3 + c1 * t3 * t3 * t3)));
                *(float4*)(C + off) = o;
            } else {  // EPI == 3
                float4 bia = *(const float4*)(bias + col);
                float4 xn  = *(const float4*)(aux1 + off);
                float4 o;
                o.x = v.x + bia.x + xn.x;
                o.y = v.y + bia.y + xn.y;
                o.z = v.z + bia.z + xn.z;
                o.w = v.w + bia.w + xn.w;
                *(float4*)(C + off) = o;
            }
        }
    }
}

// ---------------- launch --------------------------------------------------
extern "C" void kernel_launch(void* const* d_in, const int* in_sizes, int n_in,
                              void* d_out, int out_size) {
    const float* x          = (const float*)d_in[0];
    const float* velocity   = (const float*)d_in[1];
    const float* pre_norm_w = (const float*)d_in[2];
    const float* conv_k     = (const float*)d_in[3];
    const float* conv_b     = (const float*)d_in[4];
    const float* W_gate     = (const float*)d_in[5];
    const float* W_a        = (const float*)d_in[6];
    const float* lam        = (const float*)d_in[7];
    const float* W_out      = (const float*)d_in[8];
    const float* b_out      = (const float*)d_in[9];
    const float* log_beta   = (const float*)d_in[10];
    const float* ffn_norm_w = (const float*)d_in[11];
    const float* W_ff1      = (const float*)d_in[12];
    const float* b_ff1      = (const float*)d_in[13];
    const float* W_ff2      = (const float*)d_in[14];
    const float* b_ff2      = (const float*)d_in[15];

    float* out1    = (float*)d_out;          // x + ffn
    float* out_vel = out1 + BSD;             // velocity

    float *p_xnorm, *p_gatepre, *p_apre, *p_concat, *p_xnew, *p_normed, *p_hidden;
    cudaGetSymbolAddress((void**)&p_xnorm,   g_xnorm);
    cudaGetSymbolAddress((void**)&p_gatepre, g_gatepre);
    cudaGetSymbolAddress((void**)&p_apre,    g_apre);
    cudaGetSymbolAddress((void**)&p_concat,  g_concat);
    cudaGetSymbolAddress((void**)&p_xnew,    g_xnew);
    cudaGetSymbolAddress((void**)&p_normed,  g_normed);
    cudaGetSymbolAddress((void**)&p_hidden,  g_hidden);

    // 1) pre-norm
    rmsnorm_kernel<<<MM, 256>>>(x, pre_norm_w, p_xnorm);
    // 2) 8*softplus(lam)
    splam_kernel<<<4, 256>>>(lam);
    // 3,4) gate / a pre-activations
    dim3 gD(MM / 128, DD / 128);
    sgemm_kernel<0><<<gD, 256>>>(p_xnorm, W_gate, p_gatepre, MM, DD, DD,
                                 nullptr, nullptr, nullptr, nullptr, nullptr);
    sgemm_kernel<0><<<gD, 256>>>(p_xnorm, W_a, p_apre, MM, DD, DD,
                                 nullptr, nullptr, nullptr, nullptr, nullptr);
    // 5) conv + gating elementwise
    gating_conv_kernel<<<(unsigned)(BSD / 256), 256>>>(conv_k, conv_b);
    // 6) RG-LRU scan
    scan_kernel<<<(BB * DD) / 256, 256>>>();
    // 7) mixer GEMM + velocity + residual (writes velocity output + x_new)
    sgemm_kernel<1><<<gD, 256>>>(p_concat, W_out, out_vel, MM, DD, 2 * DD,
                                 b_out, velocity, x, log_beta, p_xnew);
    // 8) ffn norm
    rmsnorm_kernel<<<MM, 256>>>(p_xnew, ffn_norm_w, p_normed);
    // 9) ff1 + gelu
    dim3 gF(MM / 128, FF / 128);
    sgemm_kernel<2><<<gF, 256>>>(p_normed, W_ff1, p_hidden, MM, FF, DD,
                                 b_ff1, nullptr, nullptr, nullptr, nullptr);
    // 10) ff2 + residual -> output 1
    sgemm_kernel<3><<<gD, 256>>>(p_hidden, W_ff2, out1, MM, DD, FF,
                                 b_ff2, p_xnew, nullptr, nullptr, nullptr);
}

// round 3
// speedup vs baseline: 3.2700x; 3.2700x over previous
#include <cuda_runtime.h>
#include <cuda_fp16.h>
#include <math.h>
#include <stdint.h>

// ---------------- problem constants ----------------
constexpr int BB = 4, SSEQ = 2048, DD = 1024, FF = 4096;
constexpr int MM = BB * SSEQ;                 // 8192
constexpr long long BSD = (long long)MM * DD; // 8388608

// ---------------- scratch (device globals; no allocation) ----------------
__device__ __half g_xn_h[MM * DD], g_xn_l[MM * DD];
__device__ float g_gatepre[MM * DD], g_apre[MM * DD];
__device__ float g_a[MM * DD], g_u[MM * DD];
__device__ __half g_cc_h[MM * 2 * DD], g_cc_l[MM * 2 * DD];
__device__ float g_xnew[MM * DD];
__device__ __half g_nm_h[MM * DD], g_nm_l[MM * DD];
__device__ __half g_hd_h[MM * FF], g_hd_l[MM * FF];
__device__ float g_splam[DD];
__device__ __half g_wt_h[12 * 1024 * 1024], g_wt_l[12 * 1024 * 1024];
// chunked-scan partials
constexpr int SCH = 16, SLEN = SSEQ / SCH;
__device__ float g_P[BB * DD * SCH], g_Hp[BB * DD * SCH], g_Cc[BB * DD * SCH];

// ---------------- helpers ----------------
__device__ __forceinline__ uint32_t s2u(const void* p) {
    uint32_t a;
    asm("{ .reg .u64 t; cvta.to.shared.u64 t, %1; cvt.u32.u64 %0, t; }" : "=r"(a) : "l"(p));
    return a;
}
__device__ __forceinline__ void cpasync16(uint32_t saddr, const void* g) {
    asm volatile("cp.async.cg.shared.global [%0], [%1], 16;" :: "r"(saddr), "l"(g));
}
__device__ __forceinline__ void cp_commit() {
    asm volatile("cp.async.commit_group;" ::: "memory");
}
template <int N>
__device__ __forceinline__ void cp_wait() {
    asm volatile("cp.async.wait_group %0;" :: "n"(N) : "memory");
}
__device__ __forceinline__ void ldsm4(uint32_t* r, uint32_t addr) {
    asm volatile("ldmatrix.sync.aligned.m8n8.x4.shared.b16 {%0,%1,%2,%3}, [%4];"
                 : "=r"(r[0]), "=r"(r[1]), "=r"(r[2]), "=r"(r[3]) : "r"(addr));
}
__device__ __forceinline__ void mma16816(float* d, const uint32_t* a, const uint32_t* b) {
    asm volatile(
        "mma.sync.aligned.m16n8k16.row.col.f32.f16.f16.f32 "
        "{%0,%1,%2,%3}, {%4,%5,%6,%7}, {%8,%9}, {%0,%1,%2,%3};"
        : "+f"(d[0]), "+f"(d[1]), "+f"(d[2]), "+f"(d[3])
        : "r"(a[0]), "r"(a[1]), "r"(a[2]), "r"(a[3]), "r"(b[0]), "r"(b[1]));
}
__device__ __forceinline__ void split_h(float v, __half& h, __half& l) {
    h = __float2half_rn(v);
    l = __float2half_rn(v - __half2float(h));
}

// ---------------- weight transpose + split: out[n][k] = W[k][n] ----------------
__global__ void transpose_split(const float* __restrict__ W, int K, int N,
                                __half* __restrict__ oh, __half* __restrict__ ol) {
    __shared__ float t[32][33];
    int n0 = blockIdx.x * 32, k0 = blockIdx.y * 32;
    #pragma unroll
    for (int i = threadIdx.y; i < 32; i += 8)
        t[i][threadIdx.x] = W[(size_t)(k0 + i) * N + n0 + threadIdx.x];
    __syncthreads();
    #pragma unroll
    for (int i = threadIdx.y; i < 32; i += 8) {
        float v = t[threadIdx.x][i];
        size_t o = (size_t)(n0 + i) * K + k0 + threadIdx.x;
        __half h, l;
        split_h(v, h, l);
        oh[o] = h;
        ol[o] = l;
    }
}

// ---------------- rmsnorm -> fp16 hi/lo ----------------
__global__ void rmsnorm_split(const float* __restrict__ in, const float* __restrict__ w,
                              __half* __restrict__ oh, __half* __restrict__ ol) {
    int row = blockIdx.x;
    const float4* ip = (const float4*)(in + (size_t)row * DD);
    float4 v = ip[threadIdx.x];
    float ss = v.x * v.x + v.y * v.y + v.z * v.z + v.w * v.w;
    #pragma unroll
    for (int o = 16; o > 0; o >>= 1) ss += __shfl_xor_sync(0xffffffffu, ss, o);
    __shared__ float ws[8];
    int lane = threadIdx.x & 31, wid = threadIdx.x >> 5;
    if (lane == 0) ws[wid] = ss;
    __syncthreads();
    if (wid == 0) {
        float s = (lane < 8) ? ws[lane] : 0.f;
        #pragma unroll
        for (int o = 4; o > 0; o >>= 1) s += __shfl_xor_sync(0xffffffffu, s, o);
        if (lane == 0) ws[0] = s;
    }
    __syncthreads();
    float rms = rsqrtf(ws[0] * (1.0f / DD) + 1e-6f);
    float4 wv = ((const float4*)w)[threadIdx.x];
    float y[4] = {v.x * rms * wv.x, v.y * rms * wv.y, v.z * rms * wv.z, v.w * rms * wv.w};
    __half h[4], l[4];
    #pragma unroll
    for (int j = 0; j < 4; j++) split_h(y[j], h[j], l[j]);
    size_t o0 = (size_t)row * DD + threadIdx.x * 4;
    *(__half2*)(oh + o0)     = __halves2half2(h[0], h[1]);
    *(__half2*)(oh + o0 + 2) = __halves2half2(h[2], h[3]);
    *(__half2*)(ol + o0)     = __halves2half2(l[0], l[1]);
    *(__half2*)(ol + o0 + 2) = __halves2half2(l[2], l[3]);
}

// ---------------- splam[d] = 8 * softplus(lam[d]) ----------------
__global__ void splam_kernel(const float* __restrict__ lam) {
    int d = blockIdx.x * blockDim.x + threadIdx.x;
    if (d < DD) {
        float l = lam[d];
        float sp = (l > 20.f) ? l : log1pf(expf(l));
        g_splam[d] = 8.0f * sp;
    }
}

// ---------------- conv + gating -> concat[:, :D] (hi/lo) + a,u ----------------
__global__ void gating_conv_kernel(const float* __restrict__ ck, const float* __restrict__ cb) {
    long long i = (long long)blockIdx.x * 256 + threadIdx.x;
    int d = (int)(i & (DD - 1));
    long long r = i >> 10;
    int t = (int)(r & (SSEQ - 1));
    float xn0 = __half2float(g_xn_h[i]) + __half2float(g_xn_l[i]);
    float4 kv = ((const float4*)ck)[d];
    float conv = cb[d] + kv.x * xn0;
    if (t >= 1) conv += kv.y * (__half2float(g_xn_h[i - DD]) + __half2float(g_xn_l[i - DD]));
    if (t >= 2) conv += kv.z * (__half2float(g_xn_h[i - 2 * DD]) + __half2float(g_xn_l[i - 2 * DD]));
    if (t >= 3) conv += kv.w * (__half2float(g_xn_h[i - 3 * DD]) + __half2float(g_xn_l[i - 3 * DD]));
    float gate = 1.f / (1.f + expf(-g_gatepre[i]));
    float sa = 1.f / (1.f + expf(-g_apre[i]));
    float a = expf(-g_splam[d] * sa);
    float u = sqrtf(fmaxf(1.f - a * a, 0.f)) * gate * xn0;
    long long co = r * (2 * DD) + d;
    __half h, l;
    split_h(conv, h, l);
    g_cc_h[co] = h;
    g_cc_l[co] = l;
    g_a[i] = a;
    g_u[i] = u;
}

// ---------------- 3-phase chunked RG-LRU scan ----------------
__global__ void scan_part1() {
    int gid = blockIdx.x * 256 + threadIdx.x;
    int d = gid & (DD - 1);
    int ch = (gid >> 10) & (SCH - 1);
    int b = gid >> 14;
    long long base = ((long long)b * SSEQ + ch * SLEN) * DD + d;
    float p = 1.f, h = 0.f;
    #pragma unroll 8
    for (int t = 0; t < SLEN; t++) {
        long long idx = base + (long long)t * DD;
        float a = g_a[idx], u = g_u[idx];
        p *= a;
        h = fmaf(a, h, u);
    }
    g_P[gid] = p;
    g_Hp[gid] = h;
}
__global__ void scan_part2() {
    int c = blockIdx.x * 256 + threadIdx.x;
    int b = c >> 10, d = c & (DD - 1);
    float carry = 0.f;
    #pragma unroll
    for (int ch = 0; ch < SCH; ch++) {
        int i = (b * SCH + ch) * DD + d;
        g_Cc[i] = carry;
        carry = fmaf(g_P[i], carry, g_Hp[i]);
    }
}
__global__ void scan_part3() {
    int gid = blockIdx.x * 256 + threadIdx.x;
    int d = gid & (DD - 1);
    int ch = (gid >> 10) & (SCH - 1);
    int b = gid >> 14;
    long long base = ((long long)b * SSEQ + ch * SLEN) * DD + d;
    float h = g_Cc[gid];
    #pragma unroll 4
    for (int t = 0; t < SLEN; t++) {
        long long idx = base + (long long)t * DD;
        h = fmaf(g_a[idx], h, g_u[idx]);
        long long row = (long long)b * SSEQ + ch * SLEN + t;
        long long co = row * (2 * DD) + DD + d;
        __half hh, ll;
        split_h(h, hh, ll);
        g_cc_h[co] = hh;
        g_cc_l[co] = ll;
    }
}

// ---------------- HMMA GEMM: 128x128 tile, BK=32, fp16 3-term split ----------------
// A [M,K] hi/lo fp16, B [N,K] hi/lo fp16 (K contiguous both). D = Ah*Bh + Al*Bh + Ah*Bl.
// EPI: 0 plain fp32; 1 mixer; 2 gelu->fp16 hi/lo; 3 +bias+aux residual
constexpr int STAGE_BYTES = 32768;  // AH 8K | AL 8K | BH 8K | BL 8K
constexpr int GEMM_SMEM = 2 * STAGE_BYTES;

template <int EPI>
__global__ void __launch_bounds__(256)
hgemm(const __half* __restrict__ Ah, const __half* __restrict__ Al,
      const __half* __restrict__ Bh, const __half* __restrict__ Bl,
      float* __restrict__ C, int N, int K,
      const float* __restrict__ bias,
      const float* __restrict__ aux1, const float* __restrict__ aux2,
      const float* __restrict__ aux3,
      float* __restrict__ out2,
      __half* __restrict__ o_hi, __half* __restrict__ o_lo) {
    extern __shared__ char sm[];
    uint32_t sb = s2u(sm);
    int tid = threadIdx.x;
    int lane = tid & 31, wid = tid >> 5;
    int wm = wid >> 2, wn = wid & 3;          // warp tile: 64x32 at (wm*64, wn*32)
    size_t mrow0 = (size_t)blockIdx.x * 128;
    size_t ncol0 = (size_t)blockIdx.y * 128;

    float acc[4][4][4];
    #pragma unroll
    for (int a = 0; a < 4; a++)
        #pragma unroll
        for (int b = 0; b < 4; b++)
            #pragma unroll
            for (int c = 0; c < 4; c++) acc[a][b][c] = 0.f;

    // stage loader: 16B chunk per thread per matrix; 2 iters cover 128 rows x 4 chunks
    auto load_stage = [&](int s, int k0) {
        uint32_t base = sb + s * STAGE_BYTES;
        #pragma unroll
        for (int i = 0; i < 2; i++) {
            int idx = tid + i * 256;
            int r = idx >> 2, c = idx & 3;
            uint32_t sw = r * 64 + ((c ^ ((r >> 1) & 3)) << 4);
            size_t ga = (mrow0 + r) * K + k0 + c * 8;
            size_t gb = (ncol0 + r) * K + k0 + c * 8;
            cpasync16(base + sw, Ah + ga);
            cpasync16(base + 8192 + sw, Al + ga);
            cpasync16(base + 16384 + sw, Bh + gb);
            cpasync16(base + 24576 + sw, Bl + gb);
        }
    };

    const int KT = K >> 5;  // BK = 32
    load_stage(0, 0);
    cp_commit();

    for (int kt = 0; kt < KT; kt++) {
        if (kt + 1 < KT) {
            load_stage((kt + 1) & 1, (kt + 1) << 5);
            cp_commit();
            cp_wait<1>();
        } else {
            cp_wait<0>();
        }
        __syncthreads();

        uint32_t base = sb + (kt & 1) * STAGE_BYTES;
        #pragma unroll
        for (int kk = 0; kk < 2; kk++) {
            uint32_t ah[4][4], al[4][4], bh[2][4], bl[2][4];
            int g = lane >> 3;
            int ar = (lane & 7) + ((g & 1) << 3);
            int ac = kk * 2 + (g >> 1);
            #pragma unroll
            for (int mi = 0; mi < 4; mi++) {
                int row = wm * 64 + mi * 16 + ar;
                uint32_t off = row * 64 + ((ac ^ ((row >> 1) & 3)) << 4);
                ldsm4(ah[mi], base + off);
                ldsm4(al[mi], base + 8192 + off);
            }
            int br = (lane & 7) + ((g >> 1) << 3);
            int bc = kk * 2 + (g & 1);
            #pragma unroll
            for (int ni = 0; ni < 2; ni++) {
                int row = wn * 32 + ni * 16 + br;
                uint32_t off = row * 64 + ((bc ^ ((row >> 1) & 3)) << 4);
                ldsm4(bh[ni], base + 16384 + off);
                ldsm4(bl[ni], base + 24576 + off);
            }
            #pragma unroll
            for (int mi = 0; mi < 4; mi++)
                #pragma unroll
                for (int n8 = 0; n8 < 4; n8++) {
                    const uint32_t* bph = &bh[n8 >> 1][(n8 & 1) * 2];
                    const uint32_t* bpl = &bl[n8 >> 1][(n8 & 1) * 2];
                    mma16816(acc[mi][n8], ah[mi], bph);
                    mma16816(acc[mi][n8], al[mi], bph);
                    mma16816(acc[mi][n8], ah[mi], bpl);
                }
        }
        __syncthreads();
    }

    // ---------------- epilogue ----------------
    const float c0g = 0.7978845608028654f, c1g = 0.044715f;
    #pragma unroll
    for (int mi = 0; mi < 4; mi++) {
        #pragma unroll
        for (int n8 = 0; n8 < 4; n8++) {
            int col = (int)ncol0 + wn * 32 + n8 * 8 + (lane & 3) * 2;
            #pragma unroll
            for (int half_ = 0; half_ < 2; half_++) {
                size_t row = mrow0 + wm * 64 + mi * 16 + (lane >> 2) + half_ * 8;
                float v0 = acc[mi][n8][half_ * 2 + 0];
                float v1 = acc[mi][n8][half_ * 2 + 1];
                size_t off = row * N + col;
                if (EPI == 0) {
                    *(float2*)(C + off) = make_float2(v0, v1);
                } else if (EPI == 1) {
                    float2 bia = *(const float2*)(bias + col);
                    float2 lb  = *(const float2*)(aux3 + col);
                    float2 vel = *(const float2*)(aux1 + off);
                    float2 xv  = *(const float2*)(aux2 + off);
                    float vn0 = fmaf(1.f / (1.f + __expf(-lb.x)), vel.x, v0 + bia.x);
                    float vn1 = fmaf(1.f / (1.f + __expf(-lb.y)), vel.y, v1 + bia.y);
                    *(float2*)(C + off) = make_float2(vn0, vn1);
                    *(float2*)(out2 + off) = make_float2(xv.x + vn0, xv.y + vn1);
                } else if (EPI == 2) {
                    float2 bia = *(const float2*)(bias + col);
                    float t0 = v0 + bia.x, t1 = v1 + bia.y;
                    t0 = 0.5f * t0 * (1.f + tanhf(c0g * (t0 + c1g * t0 * t0 * t0)));
                    t1 = 0.5f * t1 * (1.f + tanhf(c0g * (t1 + c1g * t1 * t1 * t1)));
                    __half h0, l0, h1, l1;
                    split_h(t0, h0, l0);
                    split_h(t1, h1, l1);
                    *(__half2*)(o_hi + off) = __halves2half2(h0, h1);
                    *(__half2*)(o_lo + off) = __halves2half2(l0, l1);
                } else {  // EPI == 3
                    float2 bia = *(const float2*)(bias + col);
                    float2 xn  = *(const float2*)(aux1 + off);
                    *(float2*)(C + off) = make_float2(v0 + bia.x + xn.x, v1 + bia.y + xn.y);
                }
            }
        }
    }
}

// ---------------- launch ----------------
extern "C" void kernel_launch(void* const* d_in, const int* in_sizes, int n_in,
                              void* d_out, int out_size) {
    const float* x          = (const float*)d_in[0];
    const float* velocity   = (const float*)d_in[1];
    const float* pre_norm_w = (const float*)d_in[2];
    const float* conv_k     = (const float*)d_in[3];
    const float* conv_b     = (const float*)d_in[4];
    const float* W_gate     = (const float*)d_in[5];
    const float* W_a        = (const float*)d_in[6];
    const float* lam        = (const float*)d_in[7];
    const float* W_out      = (const float*)d_in[8];
    const float* b_out      = (const float*)d_in[9];
    const float* log_beta   = (const float*)d_in[10];
    const float* ffn_norm_w = (const float*)d_in[11];
    const float* W_ff1      = (const float*)d_in[12];
    const float* b_ff1      = (const float*)d_in[13];
    const float* W_ff2      = (const float*)d_in[14];
    const float* b_ff2      = (const float*)d_in[15];

    float* out1    = (float*)d_out;
    float* out_vel = out1 + BSD;

    __half *p_xn_h, *p_xn_l, *p_cc_h, *p_cc_l, *p_nm_h, *p_nm_l, *p_hd_h, *p_hd_l,
           *p_wt_h, *p_wt_l;
    float *p_gatepre, *p_apre, *p_xnew;
    cudaGetSymbolAddress((void**)&p_xn_h, g_xn_h);
    cudaGetSymbolAddress((void**)&p_xn_l, g_xn_l);
    cudaGetSymbolAddress((void**)&p_cc_h, g_cc_h);
    cudaGetSymbolAddress((void**)&p_cc_l, g_cc_l);
    cudaGetSymbolAddress((void**)&p_nm_h, g_nm_h);
    cudaGetSymbolAddress((void**)&p_nm_l, g_nm_l);
    cudaGetSymbolAddress((void**)&p_hd_h, g_hd_h);
    cudaGetSymbolAddress((void**)&p_hd_l, g_hd_l);
    cudaGetSymbolAddress((void**)&p_wt_h, g_wt_h);
    cudaGetSymbolAddress((void**)&p_wt_l, g_wt_l);
    cudaGetSymbolAddress((void**)&p_gatepre, g_gatepre);
    cudaGetSymbolAddress((void**)&p_apre, g_apre);
    cudaGetSymbolAddress((void**)&p_xnew, g_xnew);

    cudaFuncSetAttribute(hgemm<0>, cudaFuncAttributeMaxDynamicSharedMemorySize, GEMM_SMEM);
    cudaFuncSetAttribute(hgemm<1>, cudaFuncAttributeMaxDynamicSharedMemorySize, GEMM_SMEM);
    cudaFuncSetAttribute(hgemm<2>, cudaFuncAttributeMaxDynamicSharedMemorySize, GEMM_SMEM);
    cudaFuncSetAttribute(hgemm<3>, cudaFuncAttributeMaxDynamicSharedMemorySize, GEMM_SMEM);

    // weight transpose+split (offsets in elements within g_wt)
    const size_t OFF_GATE = 0, OFF_A = 1u << 20, OFF_OUT = 2u << 20,
                 OFF_FF1 = 4u << 20, OFF_FF2 = 8u << 20;
    dim3 tb(32, 8);
    transpose_split<<<dim3(32, 32), tb>>>(W_gate, 1024, 1024, p_wt_h + OFF_GATE, p_wt_l + OFF_GATE);
    transpose_split<<<dim3(32, 32), tb>>>(W_a, 1024, 1024, p_wt_h + OFF_A, p_wt_l + OFF_A);
    transpose_split<<<dim3(32, 64), tb>>>(W_out, 2048, 1024, p_wt_h + OFF_OUT, p_wt_l + OFF_OUT);
    transpose_split<<<dim3(128, 32), tb>>>(W_ff1, 1024, 4096, p_wt_h + OFF_FF1, p_wt_l + OFF_FF1);
    transpose_split<<<dim3(32, 128), tb>>>(W_ff2, 4096, 1024, p_wt_h + OFF_FF2, p_wt_l + OFF_FF2);

    // pre-norm -> fp16 split
    rmsnorm_split<<<MM, 256>>>(x, pre_norm_w, p_xn_h, p_xn_l);
    splam_kernel<<<4, 256>>>(lam);

    // gate / a GEMMs (M=8192, N=1024, K=1024)
    dim3 gD(MM / 128, 1024 / 128);
    hgemm<0><<<gD, 256, GEMM_SMEM>>>(p_xn_h, p_xn_l, p_wt_h + OFF_GATE, p_wt_l + OFF_GATE,
                                     p_gatepre, 1024, 1024,
                                     nullptr, nullptr, nullptr, nullptr, nullptr, nullptr, nullptr);
    hgemm<0><<<gD, 256, GEMM_SMEM>>>(p_xn_h, p_xn_l, p_wt_h + OFF_A, p_wt_l + OFF_A,
                                     p_apre, 1024, 1024,
                                     nullptr, nullptr, nullptr, nullptr, nullptr, nullptr, nullptr);

    // conv + gating + scan
    gating_conv_kernel<<<(unsigned)(BSD / 256), 256>>>(conv_k, conv_b);
    scan_part1<<<BB * DD * SCH / 256, 256>>>();
    scan_part2<<<BB * DD / 256, 256>>>();
    scan_part3<<<BB * DD * SCH / 256, 256>>>();

    // mixer GEMM (K=2048) + velocity + residual
    hgemm<1><<<gD, 256, GEMM_SMEM>>>(p_cc_h, p_cc_l, p_wt_h + OFF_OUT, p_wt_l + OFF_OUT,
                                     out_vel, 1024, 2048,
                                     b_out, velocity, x, log_beta, p_xnew, nullptr, nullptr);

    // ffn norm
    rmsnorm_split<<<MM, 256>>>(p_xnew, ffn_norm_w, p_nm_h, p_nm_l);

    // ff1 + gelu -> fp16 split hidden (N=4096, K=1024)
    dim3 gF(MM / 128, 4096 / 128);
    hgemm<2><<<gF, 256, GEMM_SMEM>>>(p_nm_h, p_nm_l, p_wt_h + OFF_FF1, p_wt_l + OFF_FF1,
                                     nullptr, 4096, 1024,
                                     b_ff1, nullptr, nullptr, nullptr, nullptr, p_hd_h, p_hd_l);

    // ff2 + residual (K=4096) -> out1
    hgemm<3><<<gD, 256, GEMM_SMEM>>>(p_hd_h, p_hd_l, p_wt_h + OFF_FF2, p_wt_l + OFF_FF2,
                                     out1, 1024, 4096,
                                     b_ff2, p_xnew, nullptr, nullptr, nullptr, nullptr, nullptr);
}

// round 4
// speedup vs baseline: 4.7378x; 1.4489x over previous
#include <cuda_runtime.h>
#include <cuda_fp16.h>
#include <math.h>
#include <stdint.h>

// ---------------- problem constants ----------------
constexpr int BB = 4, SSEQ = 2048, DD = 1024, FF = 4096;
constexpr int MM = BB * SSEQ;                 // 8192
constexpr long long BSD = (long long)MM * DD; // 8388608

// ---------------- scratch (device globals; no allocation) ----------------
__device__ __half g_xn_h[MM * DD];
__device__ float  g_xnorm[MM * DD];           // fp32 x_norm for conv/gating path
__device__ float g_gatepre[MM * DD], g_apre[MM * DD];
__device__ float g_a[MM * DD], g_u[MM * DD];
__device__ __half g_cc_h[MM * 2 * DD];
__device__ float g_xnew[MM * DD];
__device__ __half g_nm_h[MM * DD];
__device__ __half g_hd_h[MM * FF];
__device__ float g_splam[DD];
__device__ __half g_wt_h[12 * 1024 * 1024], g_wt_l[12 * 1024 * 1024];
// chunked-scan partials
constexpr int SCH = 16, SLEN = SSEQ / SCH;
__device__ float g_P[BB * DD * SCH], g_Hp[BB * DD * SCH], g_Cc[BB * DD * SCH];

// ---------------- helpers ----------------
__device__ __forceinline__ uint32_t s2u(const void* p) {
    uint32_t a;
    asm("{ .reg .u64 t; cvta.to.shared.u64 t, %1; cvt.u32.u64 %0, t; }" : "=r"(a) : "l"(p));
    return a;
}
__device__ __forceinline__ void cpasync16(uint32_t saddr, const void* g) {
    asm volatile("cp.async.cg.shared.global [%0], [%1], 16;" :: "r"(saddr), "l"(g));
}
__device__ __forceinline__ void cp_commit() {
    asm volatile("cp.async.commit_group;" ::: "memory");
}
template <int N>
__device__ __forceinline__ void cp_wait() {
    asm volatile("cp.async.wait_group %0;" :: "n"(N) : "memory");
}
__device__ __forceinline__ void ldsm4(uint32_t* r, uint32_t addr) {
    asm volatile("ldmatrix.sync.aligned.m8n8.x4.shared.b16 {%0,%1,%2,%3}, [%4];"
                 : "=r"(r[0]), "=r"(r[1]), "=r"(r[2]), "=r"(r[3]) : "r"(addr));
}
__device__ __forceinline__ void mma16816(float* d, const uint32_t* a, const uint32_t* b) {
    asm volatile(
        "mma.sync.aligned.m16n8k16.row.col.f32.f16.f16.f32 "
        "{%0,%1,%2,%3}, {%4,%5,%6,%7}, {%8,%9}, {%0,%1,%2,%3};"
        : "+f"(d[0]), "+f"(d[1]), "+f"(d[2]), "+f"(d[3])
        : "r"(a[0]), "r"(a[1]), "r"(a[2]), "r"(a[3]), "r"(b[0]), "r"(b[1]));
}
__device__ __forceinline__ void split_h(float v, __half& h, __half& l) {
    h = __float2half_rn(v);
    l = __float2half_rn(v - __half2float(h));
}

// ---------------- weight transpose + split: out[n][k] = W[k][n] ----------------
__global__ void transpose_split(const float* __restrict__ W, int K, int N,
                                __half* __restrict__ oh, __half* __restrict__ ol) {
    __shared__ float t[32][33];
    int n0 = blockIdx.x * 32, k0 = blockIdx.y * 32;
    #pragma unroll
    for (int i = threadIdx.y; i < 32; i += 8)
        t[i][threadIdx.x] = W[(size_t)(k0 + i) * N + n0 + threadIdx.x];
    __syncthreads();
    #pragma unroll
    for (int i = threadIdx.y; i < 32; i += 8) {
        float v = t[threadIdx.x][i];
        size_t o = (size_t)(n0 + i) * K + k0 + threadIdx.x;
        __half h, l;
        split_h(v, h, l);
        oh[o] = h;
        ol[o] = l;
    }
}

// ---------------- rmsnorm -> fp16 hi (+ optional fp32 copy) ----------------
template <int WRITE_F32>
__global__ void rmsnorm_h(const float* __restrict__ in, const float* __restrict__ w,
                          __half* __restrict__ oh, float* __restrict__ of32) {
    int row = blockIdx.x;
    const float4* ip = (const float4*)(in + (size_t)row * DD);
    float4 v = ip[threadIdx.x];
    float ss = v.x * v.x + v.y * v.y + v.z * v.z + v.w * v.w;
    #pragma unroll
    for (int o = 16; o > 0; o >>= 1) ss += __shfl_xor_sync(0xffffffffu, ss, o);
    __shared__ float ws[8];
    int lane = threadIdx.x & 31, wid = threadIdx.x >> 5;
    if (lane == 0) ws[wid] = ss;
    __syncthreads();
    if (wid == 0) {
        float s = (lane < 8) ? ws[lane] : 0.f;
        #pragma unroll
        for (int o = 4; o > 0; o >>= 1) s += __shfl_xor_sync(0xffffffffu, s, o);
        if (lane == 0) ws[0] = s;
    }
    __syncthreads();
    float rms = rsqrtf(ws[0] * (1.0f / DD) + 1e-6f);
    float4 wv = ((const float4*)w)[threadIdx.x];
    float y[4] = {v.x * rms * wv.x, v.y * rms * wv.y, v.z * rms * wv.z, v.w * rms * wv.w};
    size_t o0 = (size_t)row * DD + threadIdx.x * 4;
    *(__half2*)(oh + o0)     = __halves2half2(__float2half_rn(y[0]), __float2half_rn(y[1]));
    *(__half2*)(oh + o0 + 2) = __halves2half2(__float2half_rn(y[2]), __float2half_rn(y[3]));
    if (WRITE_F32)
        *(float4*)(of32 + o0) = make_float4(y[0], y[1], y[2], y[3]);
}

// ---------------- splam[d] = 8 * softplus(lam[d]) ----------------
__global__ void splam_kernel(const float* __restrict__ lam) {
    int d = blockIdx.x * blockDim.x + threadIdx.x;
    if (d < DD) {
        float l = lam[d];
        float sp = (l > 20.f) ? l : log1pf(expf(l));
        g_splam[d] = 8.0f * sp;
    }
}

// ---------------- conv + gating -> concat[:, :D] (hi) + a,u ----------------
__global__ void gating_conv_kernel(const float* __restrict__ ck, const float* __restrict__ cb) {
    long long i = (long long)blockIdx.x * 256 + threadIdx.x;
    int d = (int)(i & (DD - 1));
    long long r = i >> 10;
    int t = (int)(r & (SSEQ - 1));
    float xn0 = g_xnorm[i];
    float4 kv = ((const float4*)ck)[d];
    float conv = cb[d] + kv.x * xn0;
    if (t >= 1) conv += kv.y * g_xnorm[i - DD];
    if (t >= 2) conv += kv.z * g_xnorm[i - 2 * DD];
    if (t >= 3) conv += kv.w * g_xnorm[i - 3 * DD];
    float gate = 1.f / (1.f + expf(-g_gatepre[i]));
    float sa = 1.f / (1.f + expf(-g_apre[i]));
    float a = expf(-g_splam[d] * sa);
    float u = sqrtf(fmaxf(1.f - a * a, 0.f)) * gate * xn0;
    g_cc_h[r * (2 * DD) + d] = __float2half_rn(conv);
    g_a[i] = a;
    g_u[i] = u;
}

// ---------------- 3-phase chunked RG-LRU scan ----------------
__global__ void scan_part1() {
    int gid = blockIdx.x * 256 + threadIdx.x;
    int d = gid & (DD - 1);
    int ch = (gid >> 10) & (SCH - 1);
    int b = gid >> 14;
    long long base = ((long long)b * SSEQ + ch * SLEN) * DD + d;
    float p = 1.f, h = 0.f;
    #pragma unroll 8
    for (int t = 0; t < SLEN; t++) {
        long long idx = base + (long long)t * DD;
        float a = g_a[idx], u = g_u[idx];
        p *= a;
        h = fmaf(a, h, u);
    }
    g_P[gid] = p;
    g_Hp[gid] = h;
}
__global__ void scan_part2() {
    int c = blockIdx.x * 256 + threadIdx.x;
    int b = c >> 10, d = c & (DD - 1);
    float carry = 0.f;
    #pragma unroll
    for (int ch = 0; ch < SCH; ch++) {
        int i = (b * SCH + ch) * DD + d;
        g_Cc[i] = carry;
        carry = fmaf(g_P[i], carry, g_Hp[i]);
    }
}
__global__ void scan_part3() {
    int gid = blockIdx.x * 256 + threadIdx.x;
    int d = gid & (DD - 1);
    int ch = (gid >> 10) & (SCH - 1);
    int b = gid >> 14;
    long long base = ((long long)b * SSEQ + ch * SLEN) * DD + d;
    float h = g_Cc[gid];
    #pragma unroll 4
    for (int t = 0; t < SLEN; t++) {
        long long idx = base + (long long)t * DD;
        h = fmaf(g_a[idx], h, g_u[idx]);
        long long row = (long long)b * SSEQ + ch * SLEN + t;
        g_cc_h[row * (2 * DD) + DD + d] = __float2half_rn(h);
    }
}

// ------- HMMA GEMM: 128x128 tile, BK=32, 2-term (A hi; B hi+lo) -------
// D = Ah*Bh + Ah*Bl.  A [M,K] fp16, B [N,K] fp16 hi/lo (K contiguous).
// EPI: 0 plain fp32; 1 mixer; 2 gelu->fp16 hi; 3 +bias+aux residual
constexpr int STAGE_BYTES = 24576;  // A 8K | BH 8K | BL 8K
constexpr int GEMM_SMEM = 2 * STAGE_BYTES;

template <int EPI>
__global__ void __launch_bounds__(256)
hgemm(const __half* __restrict__ Ah,
      const __half* __restrict__ Bh, const __half* __restrict__ Bl,
      float* __restrict__ C, int N, int K,
      const float* __restrict__ bias,
      const float* __restrict__ aux1, const float* __restrict__ aux2,
      const float* __restrict__ aux3,
      float* __restrict__ out2,
      __half* __restrict__ o_hi) {
    extern __shared__ char sm[];
    uint32_t sb = s2u(sm);
    int tid = threadIdx.x;
    int lane = tid & 31, wid = tid >> 5;
    int wm = wid >> 2, wn = wid & 3;          // warp tile: 64x32 at (wm*64, wn*32)
    size_t mrow0 = (size_t)blockIdx.x * 128;
    size_t ncol0 = (size_t)blockIdx.y * 128;

    float acc[4][4][4];
    #pragma unroll
    for (int a = 0; a < 4; a++)
        #pragma unroll
        for (int b = 0; b < 4; b++)
            #pragma unroll
            for (int c = 0; c < 4; c++) acc[a][b][c] = 0.f;

    auto load_stage = [&](int s, int k0) {
        uint32_t base = sb + s * STAGE_BYTES;
        #pragma unroll
        for (int i = 0; i < 2; i++) {
            int idx = tid + i * 256;
            int r = idx >> 2, c = idx & 3;
            uint32_t sw = r * 64 + ((c ^ ((r >> 1) & 3)) << 4);
            cpasync16(base + sw, Ah + (mrow0 + r) * K + k0 + c * 8);
        }
        #pragma unroll
        for (int i = 0; i < 2; i++) {
            int idx = tid + i * 256;
            int r = idx >> 2, c = idx & 3;
            uint32_t sw = r * 64 + ((c ^ ((r >> 1) & 3)) << 4);
            size_t gb = (ncol0 + r) * K + k0 + c * 8;
            cpasync16(base + 8192 + sw, Bh + gb);
            cpasync16(base + 16384 + sw, Bl + gb);
        }
    };

    const int KT = K >> 5;  // BK = 32
    load_stage(0, 0);
    cp_commit();

    for (int kt = 0; kt < KT; kt++) {
        if (kt + 1 < KT) {
            load_stage((kt + 1) & 1, (kt + 1) << 5);
            cp_commit();
            cp_wait<1>();
        } else {
            cp_wait<0>();
        }
        __syncthreads();

        uint32_t base = sb + (kt & 1) * STAGE_BYTES;
        #pragma unroll
        for (int kk = 0; kk < 2; kk++) {
            uint32_t ah[4][4], bh[2][4], bl[2][4];
            int g = lane >> 3;
            int ar = (lane & 7) + ((g & 1) << 3);
            int ac = kk * 2 + (g >> 1);
            #pragma unroll
            for (int mi = 0; mi < 4; mi++) {
                int row = wm * 64 + mi * 16 + ar;
                uint32_t off = row * 64 + ((ac ^ ((row >> 1) & 3)) << 4);
                ldsm4(ah[mi], base + off);
            }
            int br = (lane & 7) + ((g >> 1) << 3);
            int bc = kk * 2 + (g & 1);
            #pragma unroll
            for (int ni = 0; ni < 2; ni++) {
                int row = wn * 32 + ni * 16 + br;
                uint32_t off = row * 64 + ((bc ^ ((row >> 1) & 3)) << 4);
                ldsm4(bh[ni], base + 8192 + off);
                ldsm4(bl[ni], base + 16384 + off);
            }
            #pragma unroll
            for (int mi = 0; mi < 4; mi++)
                #pragma unroll
                for (int n8 = 0; n8 < 4; n8++) {
                    const uint32_t* bph = &bh[n8 >> 1][(n8 & 1) * 2];
                    const uint32_t* bpl = &bl[n8 >> 1][(n8 & 1) * 2];
                    mma16816(acc[mi][n8], ah[mi], bph);
                    mma16816(acc[mi][n8], ah[mi], bpl);
                }
        }
        __syncthreads();
    }

    // ---------------- epilogue ----------------
    const float c0g = 0.7978845608028654f, c1g = 0.044715f;
    #pragma unroll
    for (int mi = 0; mi < 4; mi++) {
        #pragma unroll
        for (int n8 = 0; n8 < 4; n8++) {
            int col = (int)ncol0 + wn * 32 + n8 * 8 + (lane & 3) * 2;
            #pragma unroll
            for (int half_ = 0; half_ < 2; half_++) {
                size_t row = mrow0 + wm * 64 + mi * 16 + (lane >> 2) + half_ * 8;
                float v0 = acc[mi][n8][half_ * 2 + 0];
                float v1 = acc[mi][n8][half_ * 2 + 1];
                size_t off = row * N + col;
                if (EPI == 0) {
                    *(float2*)(C + off) = make_float2(v0, v1);
                } else if (EPI == 1) {
                    float2 bia = *(const float2*)(bias + col);
                    float2 lb  = *(const float2*)(aux3 + col);
                    float2 vel = *(const float2*)(aux1 + off);
                    float2 xv  = *(const float2*)(aux2 + off);
                    float vn0 = fmaf(1.f / (1.f + __expf(-lb.x)), vel.x, v0 + bia.x);
                    float vn1 = fmaf(1.f / (1.f + __expf(-lb.y)), vel.y, v1 + bia.y);
                    *(float2*)(C + off) = make_float2(vn0, vn1);
                    *(float2*)(out2 + off) = make_float2(xv.x + vn0, xv.y + vn1);
                } else if (EPI == 2) {
                    float2 bia = *(const float2*)(bias + col);
                    float t0 = v0 + bia.x, t1 = v1 + bia.y;
                    t0 = 0.5f * t0 * (1.f + tanhf(c0g * (t0 + c1g * t0 * t0 * t0)));
                    t1 = 0.5f * t1 * (1.f + tanhf(c0g * (t1 + c1g * t1 * t1 * t1)));
                    *(__half2*)(o_hi + off) =
                        __halves2half2(__float2half_rn(t0), __float2half_rn(t1));
                } else {  // EPI == 3
                    float2 bia = *(const float2*)(bias + col);
                    float2 xn  = *(const float2*)(aux1 + off);
                    *(float2*)(C + off) = make_float2(v0 + bia.x + xn.x, v1 + bia.y + xn.y);
                }
            }
        }
    }
}

// ---------------- launch ----------------
extern "C" void kernel_launch(void* const* d_in, const int* in_sizes, int n_in,
                              void* d_out, int out_size) {
    const float* x          = (const float*)d_in[0];
    const float* velocity   = (const float*)d_in[1];
    const float* pre_norm_w = (const float*)d_in[2];
    const float* conv_k     = (const float*)d_in[3];
    const float* conv_b     = (const float*)d_in[4];
    const float* W_gate     = (const float*)d_in[5];
    const float* W_a        = (const float*)d_in[6];
    const float* lam        = (const float*)d_in[7];
    const float* W_out      = (const float*)d_in[8];
    const float* b_out      = (const float*)d_in[9];
    const float* log_beta   = (const float*)d_in[10];
    const float* ffn_norm_w = (const float*)d_in[11];
    const float* W_ff1      = (const float*)d_in[12];
    const float* b_ff1      = (const float*)d_in[13];
    const float* W_ff2      = (const float*)d_in[14];
    const float* b_ff2      = (const float*)d_in[15];

    float* out1    = (float*)d_out;
    float* out_vel = out1 + BSD;

    __half *p_xn_h, *p_cc_h, *p_nm_h, *p_hd_h, *p_wt_h, *p_wt_l;
    float *p_xnorm, *p_gatepre, *p_apre, *p_xnew;
    cudaGetSymbolAddress((void**)&p_xn_h, g_xn_h);
    cudaGetSymbolAddress((void**)&p_xnorm, g_xnorm);
    cudaGetSymbolAddress((void**)&p_cc_h, g_cc_h);
    cudaGetSymbolAddress((void**)&p_nm_h, g_nm_h);
    cudaGetSymbolAddress((void**)&p_hd_h, g_hd_h);
    cudaGetSymbolAddress((void**)&p_wt_h, g_wt_h);
    cudaGetSymbolAddress((void**)&p_wt_l, g_wt_l);
    cudaGetSymbolAddress((void**)&p_gatepre, g_gatepre);
    cudaGetSymbolAddress((void**)&p_apre, g_apre);
    cudaGetSymbolAddress((void**)&p_xnew, g_xnew);

    cudaFuncSetAttribute(hgemm<0>, cudaFuncAttributeMaxDynamicSharedMemorySize, GEMM_SMEM);
    cudaFuncSetAttribute(hgemm<1>, cudaFuncAttributeMaxDynamicSharedMemorySize, GEMM_SMEM);
    cudaFuncSetAttribute(hgemm<2>, cudaFuncAttributeMaxDynamicSharedMemorySize, GEMM_SMEM);
    cudaFuncSetAttribute(hgemm<3>, cudaFuncAttributeMaxDynamicSharedMemorySize, GEMM_SMEM);

    // weight transpose+split (offsets in elements within g_wt)
    const size_t OFF_GATE = 0, OFF_A = 1u << 20, OFF_OUT = 2u << 20,
                 OFF_FF1 = 4u << 20, OFF_FF2 = 8u << 20;
    dim3 tb(32, 8);
    transpose_split<<<dim3(32, 32), tb>>>(W_gate, 1024, 1024, p_wt_h + OFF_GATE, p_wt_l + OFF_GATE);
    transpose_split<<<dim3(32, 32), tb>>>(W_a, 1024, 1024, p_wt_h + OFF_A, p_wt_l + OFF_A);
    transpose_split<<<dim3(32, 64), tb>>>(W_out, 2048, 1024, p_wt_h + OFF_OUT, p_wt_l + OFF_OUT);
    transpose_split<<<dim3(128, 32), tb>>>(W_ff1, 1024, 4096, p_wt_h + OFF_FF1, p_wt_l + OFF_FF1);
    transpose_split<<<dim3(32, 128), tb>>>(W_ff2, 4096, 1024, p_wt_h + OFF_FF2, p_wt_l + OFF_FF2);

    // pre-norm -> fp16 hi + fp32 copy (conv/gating path)
    rmsnorm_h<1><<<MM, 256>>>(x, pre_norm_w, p_xn_h, p_xnorm);
    splam_kernel<<<4, 256>>>(lam);

    // gate / a GEMMs (M=8192, N=1024, K=1024)
    dim3 gD(MM / 128, 1024 / 128);
    hgemm<0><<<gD, 256, GEMM_SMEM>>>(p_xn_h, p_wt_h + OFF_GATE, p_wt_l + OFF_GATE,
                                     p_gatepre, 1024, 1024,
                                     nullptr, nullptr, nullptr, nullptr, nullptr, nullptr);
    hgemm<0><<<gD, 256, GEMM_SMEM>>>(p_xn_h, p_wt_h + OFF_A, p_wt_l + OFF_A,
                                     p_apre, 1024, 1024,
                                     nullptr, nullptr, nullptr, nullptr, nullptr, nullptr);

    // conv + gating + scan
    gating_conv_kernel<<<(unsigned)(BSD / 256), 256>>>(conv_k, conv_b);
    scan_part1<<<BB * DD * SCH / 256, 256>>>();
    scan_part2<<<BB * DD / 256, 256>>>();
    scan_part3<<<BB * DD * SCH / 256, 256>>>();

    // mixer GEMM (K=2048) + velocity + residual
    hgemm<1><<<gD, 256, GEMM_SMEM>>>(p_cc_h, p_wt_h + OFF_OUT, p_wt_l + OFF_OUT,
                                     out_vel, 1024, 2048,
                                     b_out, velocity, x, log_beta, p_xnew, nullptr);

    // ffn norm (hi only)
    rmsnorm_h<0><<<MM, 256>>>(p_xnew, ffn_norm_w, p_nm_h, nullptr);

    // ff1 + gelu -> fp16 hidden (N=4096, K=1024)
    dim3 gF(MM / 128, 4096 / 128);
    hgemm<2><<<gF, 256, GEMM_SMEM>>>(p_nm_h, p_wt_h + OFF_FF1, p_wt_l + OFF_FF1,
                                     nullptr, 4096, 1024,
                                     b_ff1, nullptr, nullptr, nullptr, nullptr, p_hd_h);

    // ff2 + residual (K=4096) -> out1
    hgemm<3><<<gD, 256, GEMM_SMEM>>>(p_hd_h, p_wt_h + OFF_FF2, p_wt_l + OFF_FF2,
                                     out1, 1024, 4096,
                                     b_ff2, p_xnew, nullptr, nullptr, nullptr, nullptr);
}

// round 5
// speedup vs baseline: 5.4593x; 1.1523x over previous
#include <cuda_runtime.h>
#include <cuda_fp16.h>
#include <math.h>
#include <stdint.h>

// ---------------- problem constants ----------------
constexpr int BB = 4, SSEQ = 2048, DD = 1024, FF = 4096;
constexpr int MM = BB * SSEQ;                 // 8192
constexpr long long BSD = (long long)MM * DD; // 8388608

// ---------------- scratch (device globals; no allocation) ----------------
__device__ __half g_xn_h[MM * DD];
__device__ float  g_xnorm[MM * DD];
__device__ float g_gpre[MM * 2 * DD];         // [gate | a] pre-activations, N=2048
__device__ float g_a[MM * DD], g_u[MM * DD];
__device__ __half g_cc_h[MM * 2 * DD];
__device__ float g_xnew[MM * DD];
__device__ __half g_nm_h[MM * DD];
__device__ __half g_hd_h[MM * FF];
__device__ __half g_wt_h[12 * 1024 * 1024], g_wt_l[4 * 1024 * 1024];
// chunked-scan partials
constexpr int SCH = 16, SLEN = SSEQ / SCH;
__device__ float g_P[BB * DD * SCH], g_Hp[BB * DD * SCH], g_Cc[BB * DD * SCH];

// ---------------- helpers ----------------
__device__ __forceinline__ uint32_t s2u(const void* p) {
    uint32_t a;
    asm("{ .reg .u64 t; cvta.to.shared.u64 t, %1; cvt.u32.u64 %0, t; }" : "=r"(a) : "l"(p));
    return a;
}
__device__ __forceinline__ void cpasync16(uint32_t saddr, const void* g) {
    asm volatile("cp.async.cg.shared.global [%0], [%1], 16;" :: "r"(saddr), "l"(g));
}
__device__ __forceinline__ void cp_commit() {
    asm volatile("cp.async.commit_group;" ::: "memory");
}
template <int N>
__device__ __forceinline__ void cp_wait() {
    asm volatile("cp.async.wait_group %0;" :: "n"(N) : "memory");
}
__device__ __forceinline__ void ldsm4(uint32_t* r, uint32_t addr) {
    asm volatile("ldmatrix.sync.aligned.m8n8.x4.shared.b16 {%0,%1,%2,%3}, [%4];"
                 : "=r"(r[0]), "=r"(r[1]), "=r"(r[2]), "=r"(r[3]) : "r"(addr));
}
__device__ __forceinline__ void mma16816(float* d, const uint32_t* a, const uint32_t* b) {
    asm volatile(
        "mma.sync.aligned.m16n8k16.row.col.f32.f16.f16.f32 "
        "{%0,%1,%2,%3}, {%4,%5,%6,%7}, {%8,%9}, {%0,%1,%2,%3};"
        : "+f"(d[0]), "+f"(d[1]), "+f"(d[2]), "+f"(d[3])
        : "r"(a[0]), "r"(a[1]), "r"(a[2]), "r"(a[3]), "r"(b[0]), "r"(b[1]));
}
__device__ __forceinline__ void split_h(float v, __half& h, __half& l) {
    h = __float2half_rn(v);
    l = __float2half_rn(v - __half2float(h));
}

// ------- weight transpose (+optional split): out[n][k] = W[k][n] -------
template <bool SPLIT>
__global__ void transpose_split(const float* __restrict__ W, int K, int N,
                                __half* __restrict__ oh, __half* __restrict__ ol) {
    __shared__ float t[32][33];
    int n0 = blockIdx.x * 32, k0 = blockIdx.y * 32;
    int tid = threadIdx.x;
    // load 32x32 tile: 1024 floats, 256 threads x 4
    #pragma unroll
    for (int i = 0; i < 4; i++) {
        int idx = tid + i * 256;
        int kr = idx >> 5, nc = idx & 31;
        t[kr][nc] = W[(size_t)(k0 + kr) * N + n0 + nc];
    }
    __syncthreads();
    // write transposed as half2 along k
    #pragma unroll
    for (int i = 0; i < 2; i++) {
        int idx = tid + i * 256;            // < 512
        int nr = idx >> 4, kp = idx & 15;
        float v0 = t[kp * 2][nr], v1 = t[kp * 2 + 1][nr];
        size_t o = (size_t)(n0 + nr) * K + k0 + kp * 2;
        if (SPLIT) {
            __half h0, l0, h1, l1;
            split_h(v0, h0, l0);
            split_h(v1, h1, l1);
            *(__half2*)(oh + o) = __halves2half2(h0, h1);
            *(__half2*)(ol + o) = __halves2half2(l0, l1);
        } else {
            *(__half2*)(oh + o) = __halves2half2(__float2half_rn(v0), __float2half_rn(v1));
        }
    }
}

// ---------------- rmsnorm -> fp16 hi (+ optional fp32 copy) ----------------
template <int WRITE_F32>
__global__ void rmsnorm_h(const float* __restrict__ in, const float* __restrict__ w,
                          __half* __restrict__ oh, float* __restrict__ of32) {
    int row = blockIdx.x;
    const float4* ip = (const float4*)(in + (size_t)row * DD);
    float4 v = ip[threadIdx.x];
    float ss = v.x * v.x + v.y * v.y + v.z * v.z + v.w * v.w;
    #pragma unroll
    for (int o = 16; o > 0; o >>= 1) ss += __shfl_xor_sync(0xffffffffu, ss, o);
    __shared__ float ws[8];
    int lane = threadIdx.x & 31, wid = threadIdx.x >> 5;
    if (lane == 0) ws[wid] = ss;
    __syncthreads();
    if (wid == 0) {
        float s = (lane < 8) ? ws[lane] : 0.f;
        #pragma unroll
        for (int o = 4; o > 0; o >>= 1) s += __shfl_xor_sync(0xffffffffu, s, o);
        if (lane == 0) ws[0] = s;
    }
    __syncthreads();
    float rms = rsqrtf(ws[0] * (1.0f / DD) + 1e-6f);
    float4 wv = ((const float4*)w)[threadIdx.x];
    float y[4] = {v.x * rms * wv.x, v.y * rms * wv.y, v.z * rms * wv.z, v.w * rms * wv.w};
    size_t o0 = (size_t)row * DD + threadIdx.x * 4;
    *(__half2*)(oh + o0)     = __halves2half2(__float2half_rn(y[0]), __float2half_rn(y[1]));
    *(__half2*)(oh + o0 + 2) = __halves2half2(__float2half_rn(y[2]), __float2half_rn(y[3]));
    if (WRITE_F32)
        *(float4*)(of32 + o0) = make_float4(y[0], y[1], y[2], y[3]);
}

// ------- fused: conv + gating + scan chunk-partials (thread = b,ch,d) -------
__global__ void gscan1_kernel(const float* __restrict__ ck, const float* __restrict__ cb,
                              const float* __restrict__ lam) {
    int gid = blockIdx.x * 256 + threadIdx.x;      // (b*SCH + ch)*DD + d
    int d = gid & (DD - 1);
    int ch = (gid >> 10) & (SCH - 1);
    int b = gid >> 14;
    float l = lam[d];
    float splam = 8.0f * ((l > 20.f) ? l : log1pf(expf(l)));
    float4 kv = ((const float4*)ck)[d];
    float cbias = cb[d];

    long long r0 = (long long)b * SSEQ + ch * SLEN;
    long long xbase = r0 * DD + d;
    // preload conv taps
    float xm1 = 0.f, xm2 = 0.f, xm3 = 0.f;
    if (ch > 0) {
        xm1 = g_xnorm[xbase - DD];
        xm2 = g_xnorm[xbase - 2 * DD];
        xm3 = g_xnorm[xbase - 3 * DD];
    }
    float p = 1.f, h = 0.f;
    #pragma unroll 4
    for (int t = 0; t < SLEN; t++) {
        long long i = xbase + (long long)t * DD;
        long long r = r0 + t;
        float xn = g_xnorm[i];
        float conv = cbias + kv.x * xn + kv.y * xm1 + kv.z * xm2 + kv.w * xm3;
        float gate = 1.f / (1.f + expf(-g_gpre[r * 2048 + d]));
        float sa   = 1.f / (1.f + expf(-g_gpre[r * 2048 + 1024 + d]));
        float a = expf(-splam * sa);
        float u = sqrtf(fmaxf(1.f - a * a, 0.f)) * gate * xn;
        g_cc_h[r * (2 * DD) + d] = __float2half_rn(conv);
        g_a[i] = a;
        g_u[i] = u;
        p *= a;
        h = fmaf(a, h, u);
        xm3 = xm2; xm2 = xm1; xm1 = xn;
    }
    g_P[gid] = p;
    g_Hp[gid] = h;
}

__global__ void scan_part2() {
    int c = blockIdx.x * 256 + threadIdx.x;
    int b = c >> 10, d = c & (DD - 1);
    float carry = 0.f;
    #pragma unroll
    for (int ch = 0; ch < SCH; ch++) {
        int i = (b * SCH + ch) * DD + d;
        g_Cc[i] = carry;
        carry = fmaf(g_P[i], carry, g_Hp[i]);
    }
}
__global__ void scan_part3() {
    int gid = blockIdx.x * 256 + threadIdx.x;
    int d = gid & (DD - 1);
    int ch = (gid >> 10) & (SCH - 1);
    int b = gid >> 14;
    long long base = ((long long)b * SSEQ + ch * SLEN) * DD + d;
    float h = g_Cc[gid];
    #pragma unroll 4
    for (int t = 0; t < SLEN; t++) {
        long long idx = base + (long long)t * DD;
        h = fmaf(g_a[idx], h, g_u[idx]);
        long long row = (long long)b * SSEQ + ch * SLEN + t;
        g_cc_h[row * (2 * DD) + DD + d] = __float2half_rn(h);
    }
}

// ------- HMMA GEMM: 128x128 tile, BK=32, NTERM = 1 or 2 weight terms -------
// D = Ah*Bh (+ Ah*Bl if NTERM==2).  A [M,K] fp16, B [N,K] fp16 (K contiguous).
// 3-stage cp.async pipeline, one __syncthreads per K-iter.
// EPI: 0 plain fp32; 1 mixer; 2 gelu->fp16 hi; 3 +bias+aux residual
template <int EPI, int NTERM>
__global__ void __launch_bounds__(256)
hgemm(const __half* __restrict__ Ah,
      const __half* __restrict__ Bh, const __half* __restrict__ Bl,
      float* __restrict__ C, int N, int K,
      const float* __restrict__ bias,
      const float* __restrict__ aux1, const float* __restrict__ aux2,
      const float* __restrict__ aux3,
      float* __restrict__ out2,
      __half* __restrict__ o_hi) {
    constexpr int STG = (NTERM == 2) ? 24576 : 16384;
    extern __shared__ char sm[];
    uint32_t sb = s2u(sm);
    int tid = threadIdx.x;
    int lane = tid & 31, wid = tid >> 5;
    int wm = wid >> 2, wn = wid & 3;
    size_t mrow0 = (size_t)blockIdx.x * 128;
    size_t ncol0 = (size_t)blockIdx.y * 128;

    float acc[4][4][4];
    #pragma unroll
    for (int a = 0; a < 4; a++)
        #pragma unroll
        for (int b = 0; b < 4; b++)
            #pragma unroll
            for (int c = 0; c < 4; c++) acc[a][b][c] = 0.f;

    auto load_stage = [&](int s, int k0) {
        uint32_t base = sb + s * STG;
        #pragma unroll
        for (int i = 0; i < 2; i++) {
            int idx = tid + i * 256;
            int r = idx >> 2, c = idx & 3;
            uint32_t sw = r * 64 + ((c ^ ((r >> 1) & 3)) << 4);
            cpasync16(base + sw, Ah + (mrow0 + r) * K + k0 + c * 8);
            size_t gb = (ncol0 + r) * K + k0 + c * 8;
            cpasync16(base + 8192 + sw, Bh + gb);
            if (NTERM == 2) cpasync16(base + 16384 + sw, Bl + gb);
        }
    };

    const int KT = K >> 5;  // BK = 32
    load_stage(0, 0);
    cp_commit();
    load_stage(1, 32);
    cp_commit();

    for (int kt = 0; kt < KT; kt++) {
        if (kt + 1 < KT) cp_wait<1>(); else cp_wait<0>();
        __syncthreads();
        if (kt + 2 < KT) {
            int s = kt + 2;
            load_stage(s % 3, s << 5);
            cp_commit();
        }
        uint32_t base = sb + (kt % 3) * STG;
        #pragma unroll
        for (int kk = 0; kk < 2; kk++) {
            uint32_t ah[4][4], bh[2][4], bl[2][4];
            int g = lane >> 3;
            int ar = (lane & 7) + ((g & 1) << 3);
            int ac = kk * 2 + (g >> 1);
            #pragma unroll
            for (int mi = 0; mi < 4; mi++) {
                int row = wm * 64 + mi * 16 + ar;
                uint32_t off = row * 64 + ((ac ^ ((row >> 1) & 3)) << 4);
                ldsm4(ah[mi], base + off);
            }
            int br = (lane & 7) + ((g >> 1) << 3);
            int bc = kk * 2 + (g & 1);
            #pragma unroll
            for (int ni = 0; ni < 2; ni++) {
                int row = wn * 32 + ni * 16 + br;
                uint32_t off = row * 64 + ((bc ^ ((row >> 1) & 3)) << 4);
                ldsm4(bh[ni], base + 8192 + off);
                if (NTERM == 2) ldsm4(bl[ni], base + 16384 + off);
            }
            #pragma unroll
            for (int mi = 0; mi < 4; mi++)
                #pragma unroll
                for (int n8 = 0; n8 < 4; n8++) {
                    mma16816(acc[mi][n8], ah[mi], &bh[n8 >> 1][(n8 & 1) * 2]);
                    if (NTERM == 2)
                        mma16816(acc[mi][n8], ah[mi], &bl[n8 >> 1][(n8 & 1) * 2]);
                }
        }
    }

    // ---------------- epilogue ----------------
    const float c0g = 0.7978845608028654f, c1g = 0.044715f;
    #pragma unroll
    for (int mi = 0; mi < 4; mi++) {
        #pragma unroll
        for (int n8 = 0; n8 < 4; n8++) {
            int col = (int)ncol0 + wn * 32 + n8 * 8 + (lane & 3) * 2;
            #pragma unroll
            for (int half_ = 0; half_ < 2; half_++) {
                size_t row = mrow0 + wm * 64 + mi * 16 + (lane >> 2) + half_ * 8;
                float v0 = acc[mi][n8][half_ * 2 + 0];
                float v1 = acc[mi][n8][half_ * 2 + 1];
                size_t off = row * N + col;
                if (EPI == 0) {
                    *(float2*)(C + off) = make_float2(v0, v1);
                } else if (EPI == 1) {
                    float2 bia = *(const float2*)(bias + col);
                    float2 lb  = *(const float2*)(aux3 + col);
                    float2 vel = *(const float2*)(aux1 + off);
                    float2 xv  = *(const float2*)(aux2 + off);
                    float vn0 = fmaf(1.f / (1.f + __expf(-lb.x)), vel.x, v0 + bia.x);
                    float vn1 = fmaf(1.f / (1.f + __expf(-lb.y)), vel.y, v1 + bia.y);
                    *(float2*)(C + off) = make_float2(vn0, vn1);
                    *(float2*)(out2 + off) = make_float2(xv.x + vn0, xv.y + vn1);
                } else if (EPI == 2) {
                    float2 bia = *(const float2*)(bias + col);
                    float t0 = v0 + bia.x, t1 = v1 + bia.y;
                    t0 = 0.5f * t0 * (1.f + tanhf(c0g * (t0 + c1g * t0 * t0 * t0)));
                    t1 = 0.5f * t1 * (1.f + tanhf(c0g * (t1 + c1g * t1 * t1 * t1)));
                    *(__half2*)(o_hi + off) =
                        __halves2half2(__float2half_rn(t0), __float2half_rn(t1));
                } else {  // EPI == 3
                    float2 bia = *(const float2*)(bias + col);
                    float2 xn  = *(const float2*)(aux1 + off);
                    *(float2*)(C + off) = make_float2(v0 + bia.x + xn.x, v1 + bia.y + xn.y);
                }
            }
        }
    }
}

// ---------------- launch ----------------
extern "C" void kernel_launch(void* const* d_in, const int* in_sizes, int n_in,
                              void* d_out, int out_size) {
    const float* x          = (const float*)d_in[0];
    const float* velocity   = (const float*)d_in[1];
    const float* pre_norm_w = (const float*)d_in[2];
    const float* conv_k     = (const float*)d_in[3];
    const float* conv_b     = (const float*)d_in[4];
    const float* W_gate     = (const float*)d_in[5];
    const float* W_a        = (const float*)d_in[6];
    const float* lam        = (const float*)d_in[7];
    const float* W_out      = (const float*)d_in[8];
    const float* b_out      = (const float*)d_in[9];
    const float* log_beta   = (const float*)d_in[10];
    const float* ffn_norm_w = (const float*)d_in[11];
    const float* W_ff1      = (const float*)d_in[12];
    const float* b_ff1      = (const float*)d_in[13];
    const float* W_ff2      = (const float*)d_in[14];
    const float* b_ff2      = (const float*)d_in[15];

    float* out1    = (float*)d_out;
    float* out_vel = out1 + BSD;

    __half *p_xn_h, *p_cc_h, *p_nm_h, *p_hd_h, *p_wt_h, *p_wt_l;
    float *p_xnorm, *p_gpre, *p_xnew;
    cudaGetSymbolAddress((void**)&p_xn_h, g_xn_h);
    cudaGetSymbolAddress((void**)&p_xnorm, g_xnorm);
    cudaGetSymbolAddress((void**)&p_cc_h, g_cc_h);
    cudaGetSymbolAddress((void**)&p_nm_h, g_nm_h);
    cudaGetSymbolAddress((void**)&p_hd_h, g_hd_h);
    cudaGetSymbolAddress((void**)&p_wt_h, g_wt_h);
    cudaGetSymbolAddress((void**)&p_wt_l, g_wt_l);
    cudaGetSymbolAddress((void**)&p_gpre, g_gpre);
    cudaGetSymbolAddress((void**)&p_xnew, g_xnew);

    constexpr int SM2 = 3 * 24576;   // NTERM=2
    constexpr int SM1 = 3 * 16384;   // NTERM=1
    cudaFuncSetAttribute(hgemm<0, 2>, cudaFuncAttributeMaxDynamicSharedMemorySize, SM2);
    cudaFuncSetAttribute(hgemm<1, 2>, cudaFuncAttributeMaxDynamicSharedMemorySize, SM2);
    cudaFuncSetAttribute(hgemm<2, 1>, cudaFuncAttributeMaxDynamicSharedMemorySize, SM1);
    cudaFuncSetAttribute(hgemm<3, 1>, cudaFuncAttributeMaxDynamicSharedMemorySize, SM1);

    // weight layout in g_wt_h (elements):
    //   [0, 2M)  gate+a concatenated rows (N=2048, K=1024)  [split: lo in g_wt_l 0..2M)
    //   [2M, 4M) W_out^T (N=1024, K=2048)                   [split: lo in g_wt_l 2M..4M)
    //   [4M, 8M) W_ff1^T (N=4096, K=1024)   hi only
    //   [8M,12M) W_ff2^T (N=1024, K=4096)   hi only
    const size_t OFF_GA = 0, OFF_A2 = (size_t)1024 * 1024, OFF_OUT = (size_t)2 << 20,
                 OFF_FF1 = (size_t)4 << 20, OFF_FF2 = (size_t)8 << 20;
    transpose_split<true><<<dim3(32, 32), 256>>>(W_gate, 1024, 1024,
                                                 p_wt_h + OFF_GA, p_wt_l + OFF_GA);
    transpose_split<true><<<dim3(32, 32), 256>>>(W_a, 1024, 1024,
                                                 p_wt_h + OFF_A2, p_wt_l + OFF_A2);
    transpose_split<true><<<dim3(32, 64), 256>>>(W_out, 2048, 1024,
                                                 p_wt_h + OFF_OUT, p_wt_l + OFF_OUT);
    transpose_split<false><<<dim3(128, 32), 256>>>(W_ff1, 1024, 4096,
                                                   p_wt_h + OFF_FF1, nullptr);
    transpose_split<false><<<dim3(32, 128), 256>>>(W_ff2, 4096, 1024,
                                                   p_wt_h + OFF_FF2, nullptr);

    // pre-norm -> fp16 hi + fp32 copy
    rmsnorm_h<1><<<MM, 256>>>(x, pre_norm_w, p_xn_h, p_xnorm);

    // fused gate+a GEMM (M=8192, N=2048, K=1024), 2-term
    dim3 gGA(MM / 128, 2048 / 128);
    hgemm<0, 2><<<gGA, 256, SM2>>>(p_xn_h, p_wt_h + OFF_GA, p_wt_l + OFF_GA,
                                   p_gpre, 2048, 1024,
                                   nullptr, nullptr, nullptr, nullptr, nullptr, nullptr);

    // fused conv + gating + scan chunk partials; then chunk combine + final scan
    gscan1_kernel<<<BB * DD * SCH / 256, 256>>>(conv_k, conv_b, lam);
    scan_part2<<<BB * DD / 256, 256>>>();
    scan_part3<<<BB * DD * SCH / 256, 256>>>();

    // mixer GEMM (K=2048) + velocity + residual, 2-term
    dim3 gD(MM / 128, 1024 / 128);
    hgemm<1, 2><<<gD, 256, SM2>>>(p_cc_h, p_wt_h + OFF_OUT, p_wt_l + OFF_OUT,
                                  out_vel, 1024, 2048,
                                  b_out, velocity, x, log_beta, p_xnew, nullptr);

    // ffn norm (hi only)
    rmsnorm_h<0><<<MM, 256>>>(p_xnew, ffn_norm_w, p_nm_h, nullptr);

    // ff1 + gelu -> fp16 hidden (N=4096, K=1024), 1-term
    dim3 gF(MM / 128, 4096 / 128);
    hgemm<2, 1><<<gF, 256, SM1>>>(p_nm_h, p_wt_h + OFF_FF1, nullptr,
                                  nullptr, 4096, 1024,
                                  b_ff1, nullptr, nullptr, nullptr, nullptr, p_hd_h);

    // ff2 + residual (K=4096) -> out1, 1-term
    hgemm<3, 1><<<gD, 256, SM1>>>(p_hd_h, p_wt_h + OFF_FF2, nullptr,
                                  out1, 1024, 4096,
                                  b_ff2, p_xnew, nullptr, nullptr, nullptr, nullptr);
}

// round 6
// speedup vs baseline: 6.2165x; 1.1387x over previous
#include <cuda_runtime.h>
#include <cuda_fp16.h>
#include <math.h>
#include <stdint.h>

// ---------------- problem constants ----------------
constexpr int BB = 4, SSEQ = 2048, DD = 1024, FF = 4096;
constexpr int MM = BB * SSEQ;                 // 8192
constexpr long long BSD = (long long)MM * DD; // 8388608

// ---------------- scratch (device globals; no allocation) ----------------
__device__ __half g_xn_h[MM * DD];
__device__ float  g_xnorm[MM * DD];
__device__ float g_gpre[MM * 2 * DD];         // [gate | a] pre-activations, N=2048
__device__ float g_a[MM * DD], g_u[MM * DD];
__device__ __half g_cc_h[MM * 2 * DD];
__device__ float g_xnew[MM * DD];
__device__ __half g_nm_h[MM * DD];
__device__ __half g_hd_h[MM * FF];
__device__ __half g_wt_h[12 * 1024 * 1024];
// chunked-scan partials
constexpr int SCH = 16, SLEN = SSEQ / SCH;
__device__ float g_P[BB * DD * SCH], g_Hp[BB * DD * SCH], g_Cc[BB * DD * SCH];

// ---------------- helpers ----------------
__device__ __forceinline__ uint32_t s2u(const void* p) {
    uint32_t a;
    asm("{ .reg .u64 t; cvta.to.shared.u64 t, %1; cvt.u32.u64 %0, t; }" : "=r"(a) : "l"(p));
    return a;
}
__device__ __forceinline__ void cpasync16(uint32_t saddr, const void* g) {
    asm volatile("cp.async.cg.shared.global [%0], [%1], 16;" :: "r"(saddr), "l"(g));
}
__device__ __forceinline__ void cp_commit() {
    asm volatile("cp.async.commit_group;" ::: "memory");
}
template <int N>
__device__ __forceinline__ void cp_wait() {
    asm volatile("cp.async.wait_group %0;" :: "n"(N) : "memory");
}
__device__ __forceinline__ void ldsm4(uint32_t* r, uint32_t addr) {
    asm volatile("ldmatrix.sync.aligned.m8n8.x4.shared.b16 {%0,%1,%2,%3}, [%4];"
                 : "=r"(r[0]), "=r"(r[1]), "=r"(r[2]), "=r"(r[3]) : "r"(addr));
}
__device__ __forceinline__ void mma16816(float* d, const uint32_t* a, const uint32_t* b) {
    asm volatile(
        "mma.sync.aligned.m16n8k16.row.col.f32.f16.f16.f32 "
        "{%0,%1,%2,%3}, {%4,%5,%6,%7}, {%8,%9}, {%0,%1,%2,%3};"
        : "+f"(d[0]), "+f"(d[1]), "+f"(d[2]), "+f"(d[3])
        : "r"(a[0]), "r"(a[1]), "r"(a[2]), "r"(a[3]), "r"(b[0]), "r"(b[1]));
}

// ------- weight transpose: out[n][k] = fp16(W[k][n]) -------
__global__ void transpose_h(const float* __restrict__ W, int K, int N,
                            __half* __restrict__ oh) {
    __shared__ float t[32][33];
    int n0 = blockIdx.x * 32, k0 = blockIdx.y * 32;
    int tid = threadIdx.x;
    #pragma unroll
    for (int i = 0; i < 4; i++) {
        int idx = tid + i * 256;
        int kr = idx >> 5, nc = idx & 31;
        t[kr][nc] = W[(size_t)(k0 + kr) * N + n0 + nc];
    }
    __syncthreads();
    #pragma unroll
    for (int i = 0; i < 2; i++) {
        int idx = tid + i * 256;            // < 512
        int nr = idx >> 4, kp = idx & 15;
        float v0 = t[kp * 2][nr], v1 = t[kp * 2 + 1][nr];
        size_t o = (size_t)(n0 + nr) * K + k0 + kp * 2;
        *(__half2*)(oh + o) = __halves2half2(__float2half_rn(v0), __float2half_rn(v1));
    }
}

// ---------------- rmsnorm -> fp16 hi (+ optional fp32 copy) ----------------
template <int WRITE_F32>
__global__ void rmsnorm_h(const float* __restrict__ in, const float* __restrict__ w,
                          __half* __restrict__ oh, float* __restrict__ of32) {
    int row = blockIdx.x;
    const float4* ip = (const float4*)(in + (size_t)row * DD);
    float4 v = ip[threadIdx.x];
    float ss = v.x * v.x + v.y * v.y + v.z * v.z + v.w * v.w;
    #pragma unroll
    for (int o = 16; o > 0; o >>= 1) ss += __shfl_xor_sync(0xffffffffu, ss, o);
    __shared__ float ws[8];
    int lane = threadIdx.x & 31, wid = threadIdx.x >> 5;
    if (lane == 0) ws[wid] = ss;
    __syncthreads();
    if (wid == 0) {
        float s = (lane < 8) ? ws[lane] : 0.f;
        #pragma unroll
        for (int o = 4; o > 0; o >>= 1) s += __shfl_xor_sync(0xffffffffu, s, o);
        if (lane == 0) ws[0] = s;
    }
    __syncthreads();
    float rms = rsqrtf(ws[0] * (1.0f / DD) + 1e-6f);
    float4 wv = ((const float4*)w)[threadIdx.x];
    float y[4] = {v.x * rms * wv.x, v.y * rms * wv.y, v.z * rms * wv.z, v.w * rms * wv.w};
    size_t o0 = (size_t)row * DD + threadIdx.x * 4;
    *(__half2*)(oh + o0)     = __halves2half2(__float2half_rn(y[0]), __float2half_rn(y[1]));
    *(__half2*)(oh + o0 + 2) = __halves2half2(__float2half_rn(y[2]), __float2half_rn(y[3]));
    if (WRITE_F32)
        *(float4*)(of32 + o0) = make_float4(y[0], y[1], y[2], y[3]);
}

// ------- fused: conv + gating + scan chunk-partials (thread = b,ch,d) -------
__global__ void gscan1_kernel(const float* __restrict__ ck, const float* __restrict__ cb,
                              const float* __restrict__ lam) {
    int gid = blockIdx.x * 256 + threadIdx.x;      // (b*SCH + ch)*DD + d
    int d = gid & (DD - 1);
    int ch = (gid >> 10) & (SCH - 1);
    int b = gid >> 14;
    float l = lam[d];
    float splam = 8.0f * ((l > 20.f) ? l : log1pf(expf(l)));
    float4 kv = ((const float4*)ck)[d];
    float cbias = cb[d];

    long long r0 = (long long)b * SSEQ + ch * SLEN;
    long long xbase = r0 * DD + d;
    float xm1 = 0.f, xm2 = 0.f, xm3 = 0.f;
    if (ch > 0) {
        xm1 = g_xnorm[xbase - DD];
        xm2 = g_xnorm[xbase - 2 * DD];
        xm3 = g_xnorm[xbase - 3 * DD];
    }
    float p = 1.f, h = 0.f;
    #pragma unroll 4
    for (int t = 0; t < SLEN; t++) {
        long long i = xbase + (long long)t * DD;
        long long r = r0 + t;
        float xn = g_xnorm[i];
        float conv = cbias + kv.x * xn + kv.y * xm1 + kv.z * xm2 + kv.w * xm3;
        float gate = 1.f / (1.f + expf(-g_gpre[r * 2048 + d]));
        float sa   = 1.f / (1.f + expf(-g_gpre[r * 2048 + 1024 + d]));
        float a = expf(-splam * sa);
        float u = sqrtf(fmaxf(1.f - a * a, 0.f)) * gate * xn;
        g_cc_h[r * (2 * DD) + d] = __float2half_rn(conv);
        g_a[i] = a;
        g_u[i] = u;
        p *= a;
        h = fmaf(a, h, u);
        xm3 = xm2; xm2 = xm1; xm1 = xn;
    }
    g_P[gid] = p;
    g_Hp[gid] = h;
}

__global__ void scan_part2() {
    int c = blockIdx.x * 256 + threadIdx.x;
    int b = c >> 10, d = c & (DD - 1);
    float carry = 0.f;
    #pragma unroll
    for (int ch = 0; ch < SCH; ch++) {
        int i = (b * SCH + ch) * DD + d;
        g_Cc[i] = carry;
        carry = fmaf(g_P[i], carry, g_Hp[i]);
    }
}
__global__ void scan_part3() {
    int gid = blockIdx.x * 256 + threadIdx.x;
    int d = gid & (DD - 1);
    int ch = (gid >> 10) & (SCH - 1);
    int b = gid >> 14;
    long long base = ((long long)b * SSEQ + ch * SLEN) * DD + d;
    float h = g_Cc[gid];
    #pragma unroll 4
    for (int t = 0; t < SLEN; t++) {
        long long idx = base + (long long)t * DD;
        h = fmaf(g_a[idx], h, g_u[idx]);
        long long row = (long long)b * SSEQ + ch * SLEN + t;
        g_cc_h[row * (2 * DD) + DD + d] = __float2half_rn(h);
    }
}

// ------- HMMA GEMM: 128x128 tile, BK=32, plain fp16, 3-stage cp.async -------
// grid: x = N-blocks (so concurrent CTAs share the A row-block via L2), y = M-blocks
// EPI: 0 plain fp32; 1 mixer; 2 gelu->fp16; 3 +bias+aux residual
constexpr int STG = 16384;           // A 8K | B 8K
constexpr int GEMM_SMEM = 3 * STG;   // 48 KB

template <int EPI>
__global__ void __launch_bounds__(256)
hgemm(const __half* __restrict__ Ah, const __half* __restrict__ Bh,
      float* __restrict__ C, int N, int K,
      const float* __restrict__ bias,
      const float* __restrict__ aux1, const float* __restrict__ aux2,
      const float* __restrict__ aux3,
      float* __restrict__ out2,
      __half* __restrict__ o_hi) {
    extern __shared__ char sm[];
    uint32_t sb = s2u(sm);
    int tid = threadIdx.x;
    int lane = tid & 31, wid = tid >> 5;
    int wm = wid >> 2, wn = wid & 3;
    size_t mrow0 = (size_t)blockIdx.y * 128;
    size_t ncol0 = (size_t)blockIdx.x * 128;

    float acc[4][4][4];
    #pragma unroll
    for (int a = 0; a < 4; a++)
        #pragma unroll
        for (int b = 0; b < 4; b++)
            #pragma unroll
            for (int c = 0; c < 4; c++) acc[a][b][c] = 0.f;

    auto load_stage = [&](int s, int k0) {
        uint32_t base = sb + s * STG;
        #pragma unroll
        for (int i = 0; i < 2; i++) {
            int idx = tid + i * 256;
            int r = idx >> 2, c = idx & 3;
            uint32_t sw = r * 64 + ((c ^ ((r >> 1) & 3)) << 4);
            cpasync16(base + sw, Ah + (mrow0 + r) * K + k0 + c * 8);
            cpasync16(base + 8192 + sw, Bh + (ncol0 + r) * K + k0 + c * 8);
        }
    };

    const int KT = K >> 5;  // BK = 32
    load_stage(0, 0);
    cp_commit();
    load_stage(1, 32);
    cp_commit();

    for (int kt = 0; kt < KT; kt++) {
        if (kt + 1 < KT) cp_wait<1>(); else cp_wait<0>();
        __syncthreads();
        if (kt + 2 < KT) {
            int s = kt + 2;
            load_stage(s % 3, s << 5);
            cp_commit();
        }
        uint32_t base = sb + (kt % 3) * STG;
        #pragma unroll
        for (int kk = 0; kk < 2; kk++) {
            uint32_t ah[4][4], bh[2][4];
            int g = lane >> 3;
            int ar = (lane & 7) + ((g & 1) << 3);
            int ac = kk * 2 + (g >> 1);
            #pragma unroll
            for (int mi = 0; mi < 4; mi++) {
                int row = wm * 64 + mi * 16 + ar;
                uint32_t off = row * 64 + ((ac ^ ((row >> 1) & 3)) << 4);
                ldsm4(ah[mi], base + off);
            }
            int br = (lane & 7) + ((g >> 1) << 3);
            int bc = kk * 2 + (g & 1);
            #pragma unroll
            for (int ni = 0; ni < 2; ni++) {
                int row = wn * 32 + ni * 16 + br;
                uint32_t off = row * 64 + ((bc ^ ((row >> 1) & 3)) << 4);
                ldsm4(bh[ni], base + 8192 + off);
            }
            #pragma unroll
            for (int mi = 0; mi < 4; mi++)
                #pragma unroll
                for (int n8 = 0; n8 < 4; n8++)
                    mma16816(acc[mi][n8], ah[mi], &bh[n8 >> 1][(n8 & 1) * 2]);
        }
    }

    // ---------------- epilogue ----------------
    const float c0g = 0.7978845608028654f, c1g = 0.044715f;
    #pragma unroll
    for (int mi = 0; mi < 4; mi++) {
        #pragma unroll
        for (int n8 = 0; n8 < 4; n8++) {
            int col = (int)ncol0 + wn * 32 + n8 * 8 + (lane & 3) * 2;
            #pragma unroll
            for (int half_ = 0; half_ < 2; half_++) {
                size_t row = mrow0 + wm * 64 + mi * 16 + (lane >> 2) + half_ * 8;
                float v0 = acc[mi][n8][half_ * 2 + 0];
                float v1 = acc[mi][n8][half_ * 2 + 1];
                size_t off = row * N + col;
                if (EPI == 0) {
                    *(float2*)(C + off) = make_float2(v0, v1);
                } else if (EPI == 1) {
                    float2 bia = *(const float2*)(bias + col);
                    float2 lb  = *(const float2*)(aux3 + col);
                    float2 vel = *(const float2*)(aux1 + off);
                    float2 xv  = *(const float2*)(aux2 + off);
                    float vn0 = fmaf(1.f / (1.f + __expf(-lb.x)), vel.x, v0 + bia.x);
                    float vn1 = fmaf(1.f / (1.f + __expf(-lb.y)), vel.y, v1 + bia.y);
                    *(float2*)(C + off) = make_float2(vn0, vn1);
                    *(float2*)(out2 + off) = make_float2(xv.x + vn0, xv.y + vn1);
                } else if (EPI == 2) {
                    float2 bia = *(const float2*)(bias + col);
                    float t0 = v0 + bia.x, t1 = v1 + bia.y;
                    t0 = 0.5f * t0 * (1.f + tanhf(c0g * (t0 + c1g * t0 * t0 * t0)));
                    t1 = 0.5f * t1 * (1.f + tanhf(c0g * (t1 + c1g * t1 * t1 * t1)));
                    *(__half2*)(o_hi + off) =
                        __halves2half2(__float2half_rn(t0), __float2half_rn(t1));
                } else {  // EPI == 3
                    float2 bia = *(const float2*)(bias + col);
                    float2 xn  = *(const float2*)(aux1 + off);
                    *(float2*)(C + off) = make_float2(v0 + bia.x + xn.x, v1 + bia.y + xn.y);
                }
            }
        }
    }
}

// ---------------- launch ----------------
extern "C" void kernel_launch(void* const* d_in, const int* in_sizes, int n_in,
                              void* d_out, int out_size) {
    const float* x          = (const float*)d_in[0];
    const float* velocity   = (const float*)d_in[1];
    const float* pre_norm_w = (const float*)d_in[2];
    const float* conv_k     = (const float*)d_in[3];
    const float* conv_b     = (const float*)d_in[4];
    const float* W_gate     = (const float*)d_in[5];
    const float* W_a        = (const float*)d_in[6];
    const float* lam        = (const float*)d_in[7];
    const float* W_out      = (const float*)d_in[8];
    const float* b_out      = (const float*)d_in[9];
    const float* log_beta   = (const float*)d_in[10];
    const float* ffn_norm_w = (const float*)d_in[11];
    const float* W_ff1      = (const float*)d_in[12];
    const float* b_ff1      = (const float*)d_in[13];
    const float* W_ff2      = (const float*)d_in[14];
    const float* b_ff2      = (const float*)d_in[15];

    float* out1    = (float*)d_out;
    float* out_vel = out1 + BSD;

    __half *p_xn_h, *p_cc_h, *p_nm_h, *p_hd_h, *p_wt_h;
    float *p_xnorm, *p_gpre, *p_xnew;
    cudaGetSymbolAddress((void**)&p_xn_h, g_xn_h);
    cudaGetSymbolAddress((void**)&p_xnorm, g_xnorm);
    cudaGetSymbolAddress((void**)&p_cc_h, g_cc_h);
    cudaGetSymbolAddress((void**)&p_nm_h, g_nm_h);
    cudaGetSymbolAddress((void**)&p_hd_h, g_hd_h);
    cudaGetSymbolAddress((void**)&p_wt_h, g_wt_h);
    cudaGetSymbolAddress((void**)&p_gpre, g_gpre);
    cudaGetSymbolAddress((void**)&p_xnew, g_xnew);

    cudaFuncSetAttribute(hgemm<0>, cudaFuncAttributeMaxDynamicSharedMemorySize, GEMM_SMEM);
    cudaFuncSetAttribute(hgemm<1>, cudaFuncAttributeMaxDynamicSharedMemorySize, GEMM_SMEM);
    cudaFuncSetAttribute(hgemm<2>, cudaFuncAttributeMaxDynamicSharedMemorySize, GEMM_SMEM);
    cudaFuncSetAttribute(hgemm<3>, cudaFuncAttributeMaxDynamicSharedMemorySize, GEMM_SMEM);

    // weight layout in g_wt_h (elements):
    //   [0, 2M)  gate+a concatenated rows (N=2048, K=1024)
    //   [2M, 4M) W_out^T (N=1024, K=2048)
    //   [4M, 8M) W_ff1^T (N=4096, K=1024)
    //   [8M,12M) W_ff2^T (N=1024, K=4096)
    const size_t OFF_GA = 0, OFF_A2 = (size_t)1024 * 1024, OFF_OUT = (size_t)2 << 20,
                 OFF_FF1 = (size_t)4 << 20, OFF_FF2 = (size_t)8 << 20;
    transpose_h<<<dim3(32, 32), 256>>>(W_gate, 1024, 1024, p_wt_h + OFF_GA);
    transpose_h<<<dim3(32, 32), 256>>>(W_a, 1024, 1024, p_wt_h + OFF_A2);
    transpose_h<<<dim3(32, 64), 256>>>(W_out, 2048, 1024, p_wt_h + OFF_OUT);
    transpose_h<<<dim3(128, 32), 256>>>(W_ff1, 1024, 4096, p_wt_h + OFF_FF1);
    transpose_h<<<dim3(32, 128), 256>>>(W_ff2, 4096, 1024, p_wt_h + OFF_FF2);

    // pre-norm -> fp16 hi + fp32 copy
    rmsnorm_h<1><<<MM, 256>>>(x, pre_norm_w, p_xn_h, p_xnorm);

    // fused gate+a GEMM (M=8192, N=2048, K=1024)
    dim3 gGA(2048 / 128, MM / 128);
    hgemm<0><<<gGA, 256, GEMM_SMEM>>>(p_xn_h, p_wt_h + OFF_GA,
                                      p_gpre, 2048, 1024,
                                      nullptr, nullptr, nullptr, nullptr, nullptr, nullptr);

    // fused conv + gating + scan chunk partials; then combine + final scan
    gscan1_kernel<<<BB * DD * SCH / 256, 256>>>(conv_k, conv_b, lam);
    scan_part2<<<BB * DD / 256, 256>>>();
    scan_part3<<<BB * DD * SCH / 256, 256>>>();

    // mixer GEMM (K=2048) + velocity + residual
    dim3 gD(1024 / 128, MM / 128);
    hgemm<1><<<gD, 256, GEMM_SMEM>>>(p_cc_h, p_wt_h + OFF_OUT,
                                     out_vel, 1024, 2048,
                                     b_out, velocity, x, log_beta, p_xnew, nullptr);

    // ffn norm
    rmsnorm_h<0><<<MM, 256>>>(p_xnew, ffn_norm_w, p_nm_h, nullptr);

    // ff1 + gelu -> fp16 hidden (N=4096, K=1024)
    dim3 gF(4096 / 128, MM / 128);
    hgemm<2><<<gF, 256, GEMM_SMEM>>>(p_nm_h, p_wt_h + OFF_FF1,
                                     nullptr, 4096, 1024,
                                     b_ff1, nullptr, nullptr, nullptr, nullptr, p_hd_h);

    // ff2 + residual (K=4096) -> out1
    hgemm<3><<<gD, 256, GEMM_SMEM>>>(p_hd_h, p_wt_h + OFF_FF2,
                                     out1, 1024, 4096,
                                     b_ff2, p_xnew, nullptr, nullptr, nullptr, nullptr);
}

// round 7
// speedup vs baseline: 6.8849x; 1.1075x over previous
#include <cuda_runtime.h>
#include <cuda_fp16.h>
#include <math.h>
#include <stdint.h>

// ---------------- problem constants ----------------
constexpr int BB = 4, SSEQ = 2048, DD = 1024, FF = 4096;
constexpr int MM = BB * SSEQ;                 // 8192
constexpr long long BSD = (long long)MM * DD; // 8388608

// ---------------- scratch (device globals; no allocation) ----------------
__device__ __half g_xn_h[MM * DD];
__device__ __half g_gate[MM * DD];            // sigmoid(gate_pre), fp16
__device__ float  g_a[MM * DD];               // recurrence coefficient, fp32
__device__ __half g_u_h[MM * DD];             // scan input, fp16
__device__ __half g_cc_h[MM * 2 * DD];        // [conv | griffin_h] fp16
__device__ float  g_xnew[MM * DD];
__device__ __half g_nm_h[MM * DD];
__device__ __half g_hd_h[MM * FF];
__device__ __half g_wt_h[12 * 1024 * 1024];
__device__ float  g_splam[DD];
// chunked-scan partials
constexpr int SCH = 16, SLEN = SSEQ / SCH;
__device__ float g_P[BB * DD * SCH], g_Hp[BB * DD * SCH], g_Cc[BB * DD * SCH];

// ---------------- helpers ----------------
__device__ __forceinline__ uint32_t s2u(const void* p) {
    uint32_t a;
    asm("{ .reg .u64 t; cvta.to.shared.u64 t, %1; cvt.u32.u64 %0, t; }" : "=r"(a) : "l"(p));
    return a;
}
__device__ __forceinline__ void cpasync16(uint32_t saddr, const void* g) {
    asm volatile("cp.async.cg.shared.global [%0], [%1], 16;" :: "r"(saddr), "l"(g));
}
__device__ __forceinline__ void cp_commit() {
    asm volatile("cp.async.commit_group;" ::: "memory");
}
template <int N>
__device__ __forceinline__ void cp_wait() {
    asm volatile("cp.async.wait_group %0;" :: "n"(N) : "memory");
}
__device__ __forceinline__ void ldsm4(uint32_t* r, uint32_t addr) {
    asm volatile("ldmatrix.sync.aligned.m8n8.x4.shared.b16 {%0,%1,%2,%3}, [%4];"
                 : "=r"(r[0]), "=r"(r[1]), "=r"(r[2]), "=r"(r[3]) : "r"(addr));
}
__device__ __forceinline__ void mma16816(float* d, const uint32_t* a, const uint32_t* b) {
    asm volatile(
        "mma.sync.aligned.m16n8k16.row.col.f32.f16.f16.f32 "
        "{%0,%1,%2,%3}, {%4,%5,%6,%7}, {%8,%9}, {%0,%1,%2,%3};"
        : "+f"(d[0]), "+f"(d[1]), "+f"(d[2]), "+f"(d[3])
        : "r"(a[0]), "r"(a[1]), "r"(a[2]), "r"(a[3]), "r"(b[0]), "r"(b[1]));
}

// ------- merged weight transpose: all 5 weights, one launch -------
__global__ void transpose_all(const float* __restrict__ Wg, const float* __restrict__ Wa,
                              const float* __restrict__ Wo, const float* __restrict__ W1,
                              const float* __restrict__ W2, __half* __restrict__ out) {
    int b = blockIdx.x;
    const float* W;
    int K, N;
    size_t off;
    int tile;
    if (b < 1024)      { W = Wg; K = 1024; N = 1024; off = 0;                    tile = b; }
    else if (b < 2048) { W = Wa; K = 1024; N = 1024; off = (size_t)1 << 20;      tile = b - 1024; }
    else if (b < 4096) { W = Wo; K = 2048; N = 1024; off = (size_t)2 << 20;      tile = b - 2048; }
    else if (b < 8192) { W = W1; K = 1024; N = 4096; off = (size_t)4 << 20;      tile = b - 4096; }
    else               { W = W2; K = 4096; N = 1024; off = (size_t)8 << 20;      tile = b - 8192; }
    int ntn = N >> 5;
    int n0 = (tile % ntn) * 32, k0 = (tile / ntn) * 32;
    __half* oh = out + off;

    __shared__ float t[32][33];
    int tid = threadIdx.x;
    #pragma unroll
    for (int i = 0; i < 4; i++) {
        int idx = tid + i * 256;
        int kr = idx >> 5, nc = idx & 31;
        t[kr][nc] = W[(size_t)(k0 + kr) * N + n0 + nc];
    }
    __syncthreads();
    #pragma unroll
    for (int i = 0; i < 2; i++) {
        int idx = tid + i * 256;
        int nr = idx >> 4, kp = idx & 15;
        float v0 = t[kp * 2][nr], v1 = t[kp * 2 + 1][nr];
        size_t o = (size_t)(n0 + nr) * K + k0 + kp * 2;
        *(__half2*)(oh + o) = __halves2half2(__float2half_rn(v0), __float2half_rn(v1));
    }
}

// ---------------- rmsnorm -> fp16 ----------------
__global__ void rmsnorm_h(const float* __restrict__ in, const float* __restrict__ w,
                          __half* __restrict__ oh) {
    int row = blockIdx.x;
    const float4* ip = (const float4*)(in + (size_t)row * DD);
    float4 v = ip[threadIdx.x];
    float ss = v.x * v.x + v.y * v.y + v.z * v.z + v.w * v.w;
    #pragma unroll
    for (int o = 16; o > 0; o >>= 1) ss += __shfl_xor_sync(0xffffffffu, ss, o);
    __shared__ float ws[8];
    int lane = threadIdx.x & 31, wid = threadIdx.x >> 5;
    if (lane == 0) ws[wid] = ss;
    __syncthreads();
    if (wid == 0) {
        float s = (lane < 8) ? ws[lane] : 0.f;
        #pragma unroll
        for (int o = 4; o > 0; o >>= 1) s += __shfl_xor_sync(0xffffffffu, s, o);
        if (lane == 0) ws[0] = s;
    }
    __syncthreads();
    float rms = rsqrtf(ws[0] * (1.0f / DD) + 1e-6f);
    float4 wv = ((const float4*)w)[threadIdx.x];
    size_t o0 = (size_t)row * DD + threadIdx.x * 4;
    *(__half2*)(oh + o0)     = __halves2half2(__float2half_rn(v.x * rms * wv.x),
                                              __float2half_rn(v.y * rms * wv.y));
    *(__half2*)(oh + o0 + 2) = __halves2half2(__float2half_rn(v.z * rms * wv.z),
                                              __float2half_rn(v.w * rms * wv.w));
}

// ---------------- splam[d] = 8 * softplus(lam[d]) ----------------
__global__ void splam_kernel(const float* __restrict__ lam) {
    int d = blockIdx.x * blockDim.x + threadIdx.x;
    if (d < DD) {
        float l = lam[d];
        float sp = (l > 20.f) ? l : log1pf(expf(l));
        g_splam[d] = 8.0f * sp;
    }
}

// ------- fused: conv + u + scan chunk-partials (thread = b,ch,d) -------
__global__ void gscan1_kernel(const float* __restrict__ ck, const float* __restrict__ cb) {
    int gid = blockIdx.x * 256 + threadIdx.x;      // (b*SCH + ch)*DD + d
    int d = gid & (DD - 1);
    int ch = (gid >> 10) & (SCH - 1);
    int b = gid >> 14;
    float4 kv = ((const float4*)ck)[d];
    float cbias = cb[d];

    long long r0 = (long long)b * SSEQ + ch * SLEN;
    long long xbase = r0 * DD + d;
    float xm1 = 0.f, xm2 = 0.f, xm3 = 0.f;
    if (ch > 0) {
        xm1 = __half2float(g_xn_h[xbase - DD]);
        xm2 = __half2float(g_xn_h[xbase - 2 * DD]);
        xm3 = __half2float(g_xn_h[xbase - 3 * DD]);
    }
    float p = 1.f, h = 0.f;
    #pragma unroll 4
    for (int t = 0; t < SLEN; t++) {
        long long i = xbase + (long long)t * DD;
        long long r = r0 + t;
        float xn = __half2float(g_xn_h[i]);
        float conv = cbias + kv.x * xn + kv.y * xm1 + kv.z * xm2 + kv.w * xm3;
        float gate = __half2float(g_gate[i]);
        float a = g_a[i];
        float u = sqrtf(fmaxf(1.f - a * a, 0.f)) * gate * xn;
        g_cc_h[r * (2 * DD) + d] = __float2half_rn(conv);
        g_u_h[i] = __float2half_rn(u);
        p *= a;
        h = fmaf(a, h, u);
        xm3 = xm2; xm2 = xm1; xm1 = xn;
    }
    g_P[gid] = p;
    g_Hp[gid] = h;
}

__global__ void scan_part2() {
    int c = blockIdx.x * 256 + threadIdx.x;
    int b = c >> 10, d = c & (DD - 1);
    float carry = 0.f;
    #pragma unroll
    for (int ch = 0; ch < SCH; ch++) {
        int i = (b * SCH + ch) * DD + d;
        g_Cc[i] = carry;
        carry = fmaf(g_P[i], carry, g_Hp[i]);
    }
}
__global__ void scan_part3() {
    int gid = blockIdx.x * 256 + threadIdx.x;
    int d = gid & (DD - 1);
    int ch = (gid >> 10) & (SCH - 1);
    int b = gid >> 14;
    long long base = ((long long)b * SSEQ + ch * SLEN) * DD + d;
    float h = g_Cc[gid];
    #pragma unroll 4
    for (int t = 0; t < SLEN; t++) {
        long long idx = base + (long long)t * DD;
        h = fmaf(g_a[idx], h, __half2float(g_u_h[idx]));
        long long row = (long long)b * SSEQ + ch * SLEN + t;
        g_cc_h[row * (2 * DD) + DD + d] = __float2half_rn(h);
    }
}

// ------- HMMA GEMM: 128x128 tile, BK=32, plain fp16, 3-stage cp.async -------
// grid: x = N-blocks, y = M-blocks (A row-block shared in L2)
// EPI: 0 plain fp32; 1 mixer; 2 gelu->fp16; 3 +bias+aux residual;
//      4 gating (gate->fp16 o_hi, a=exp(-splam*sigmoid)->fp32 C, both N-stride 1024)
constexpr int STG = 16384;           // A 8K | B 8K
constexpr int GEMM_SMEM = 3 * STG;   // 48 KB

template <int EPI>
__global__ void __launch_bounds__(256)
hgemm(const __half* __restrict__ Ah, const __half* __restrict__ Bh,
      float* __restrict__ C, int N, int K,
      const float* __restrict__ bias,
      const float* __restrict__ aux1, const float* __restrict__ aux2,
      const float* __restrict__ aux3,
      float* __restrict__ out2,
      __half* __restrict__ o_hi) {
    extern __shared__ char sm[];
    uint32_t sb = s2u(sm);
    int tid = threadIdx.x;
    int lane = tid & 31, wid = tid >> 5;
    int wm = wid >> 2, wn = wid & 3;
    size_t mrow0 = (size_t)blockIdx.y * 128;
    size_t ncol0 = (size_t)blockIdx.x * 128;

    float acc[4][4][4];
    #pragma unroll
    for (int a = 0; a < 4; a++)
        #pragma unroll
        for (int b = 0; b < 4; b++)
            #pragma unroll
            for (int c = 0; c < 4; c++) acc[a][b][c] = 0.f;

    auto load_stage = [&](int s, int k0) {
        uint32_t base = sb + s * STG;
        #pragma unroll
        for (int i = 0; i < 2; i++) {
            int idx = tid + i * 256;
            int r = idx >> 2, c = idx & 3;
            uint32_t sw = r * 64 + ((c ^ ((r >> 1) & 3)) << 4);
            cpasync16(base + sw, Ah + (mrow0 + r) * K + k0 + c * 8);
            cpasync16(base + 8192 + sw, Bh + (ncol0 + r) * K + k0 + c * 8);
        }
    };

    const int KT = K >> 5;  // BK = 32
    load_stage(0, 0);
    cp_commit();
    load_stage(1, 32);
    cp_commit();

    for (int kt = 0; kt < KT; kt++) {
        if (kt + 1 < KT) cp_wait<1>(); else cp_wait<0>();
        __syncthreads();
        if (kt + 2 < KT) {
            int s = kt + 2;
            load_stage(s % 3, s << 5);
            cp_commit();
        }
        uint32_t base = sb + (kt % 3) * STG;
        #pragma unroll
        for (int kk = 0; kk < 2; kk++) {
            uint32_t ah[4][4], bh[2][4];
            int g = lane >> 3;
            int ar = (lane & 7) + ((g & 1) << 3);
            int ac = kk * 2 + (g >> 1);
            #pragma unroll
            for (int mi = 0; mi < 4; mi++) {
                int row = wm * 64 + mi * 16 + ar;
                uint32_t off = row * 64 + ((ac ^ ((row >> 1) & 3)) << 4);
                ldsm4(ah[mi], base + off);
            }
            int br = (lane & 7) + ((g >> 1) << 3);
            int bc = kk * 2 + (g & 1);
            #pragma unroll
            for (int ni = 0; ni < 2; ni++) {
                int row = wn * 32 + ni * 16 + br;
                uint32_t off = row * 64 + ((bc ^ ((row >> 1) & 3)) << 4);
                ldsm4(bh[ni], base + 8192 + off);
            }
            #pragma unroll
            for (int mi = 0; mi < 4; mi++)
                #pragma unroll
                for (int n8 = 0; n8 < 4; n8++)
                    mma16816(acc[mi][n8], ah[mi], &bh[n8 >> 1][(n8 & 1) * 2]);
        }
    }

    // ---------------- epilogue ----------------
    const float c0g = 0.7978845608028654f, c1g = 0.044715f;
    #pragma unroll
    for (int mi = 0; mi < 4; mi++) {
        #pragma unroll
        for (int n8 = 0; n8 < 4; n8++) {
            int col = (int)ncol0 + wn * 32 + n8 * 8 + (lane & 3) * 2;
            #pragma unroll
            for (int half_ = 0; half_ < 2; half_++) {
                size_t row = mrow0 + wm * 64 + mi * 16 + (lane >> 2) + half_ * 8;
                float v0 = acc[mi][n8][half_ * 2 + 0];
                float v1 = acc[mi][n8][half_ * 2 + 1];
                size_t off = row * N + col;
                if (EPI == 0) {
                    *(float2*)(C + off) = make_float2(v0, v1);
                } else if (EPI == 1) {
                    float2 bia = *(const float2*)(bias + col);
                    float2 lb  = *(const float2*)(aux3 + col);
                    float2 vel = *(const float2*)(aux1 + off);
                    float2 xv  = *(const float2*)(aux2 + off);
                    float vn0 = fmaf(1.f / (1.f + __expf(-lb.x)), vel.x, v0 + bia.x);
                    float vn1 = fmaf(1.f / (1.f + __expf(-lb.y)), vel.y, v1 + bia.y);
                    *(float2*)(C + off) = make_float2(vn0, vn1);
                    *(float2*)(out2 + off) = make_float2(xv.x + vn0, xv.y + vn1);
                } else if (EPI == 2) {
                    float2 bia = *(const float2*)(bias + col);
                    float t0 = v0 + bia.x, t1 = v1 + bia.y;
                    t0 = 0.5f * t0 * (1.f + tanhf(c0g * (t0 + c1g * t0 * t0 * t0)));
                    t1 = 0.5f * t1 * (1.f + tanhf(c0g * (t1 + c1g * t1 * t1 * t1)));
                    *(__half2*)(o_hi + off) =
                        __halves2half2(__float2half_rn(t0), __float2half_rn(t1));
                } else if (EPI == 3) {
                    float2 bia = *(const float2*)(bias + col);
                    float2 xn  = *(const float2*)(aux1 + off);
                    *(float2*)(C + off) = make_float2(v0 + bia.x + xn.x, v1 + bia.y + xn.y);
                } else {  // EPI == 4: gating. N==2048, halves are CTA-uniform.
                    if (col < 1024) {
                        float s0 = 1.f / (1.f + __expf(-v0));
                        float s1 = 1.f / (1.f + __expf(-v1));
                        *(__half2*)(o_hi + row * 1024 + col) =
                            __halves2half2(__float2half_rn(s0), __float2half_rn(s1));
                    } else {
                        int d = col - 1024;
                        float sp0 = aux3[d], sp1 = aux3[d + 1];
                        float sa0 = 1.f / (1.f + __expf(-v0));
                        float sa1 = 1.f / (1.f + __expf(-v1));
                        float a0 = expf(-sp0 * sa0);
                        float a1 = expf(-sp1 * sa1);
                        *(float2*)(C + row * 1024 + d) = make_float2(a0, a1);
                    }
                }
            }
        }
    }
}

// ---------------- launch ----------------
extern "C" void kernel_launch(void* const* d_in, const int* in_sizes, int n_in,
                              void* d_out, int out_size) {
    const float* x          = (const float*)d_in[0];
    const float* velocity   = (const float*)d_in[1];
    const float* pre_norm_w = (const float*)d_in[2];
    const float* conv_k     = (const float*)d_in[3];
    const float* conv_b     = (const float*)d_in[4];
    const float* W_gate     = (const float*)d_in[5];
    const float* W_a        = (const float*)d_in[6];
    const float* lam        = (const float*)d_in[7];
    const float* W_out      = (const float*)d_in[8];
    const float* b_out      = (const float*)d_in[9];
    const float* log_beta   = (const float*)d_in[10];
    const float* ffn_norm_w = (const float*)d_in[11];
    const float* W_ff1      = (const float*)d_in[12];
    const float* b_ff1      = (const float*)d_in[13];
    const float* W_ff2      = (const float*)d_in[14];
    const float* b_ff2      = (const float*)d_in[15];

    float* out1    = (float*)d_out;
    float* out_vel = out1 + BSD;

    __half *p_xn_h, *p_gate, *p_cc_h, *p_nm_h, *p_hd_h, *p_wt_h;
    float *p_a, *p_xnew, *p_splam;
    cudaGetSymbolAddress((void**)&p_xn_h, g_xn_h);
    cudaGetSymbolAddress((void**)&p_gate, g_gate);
    cudaGetSymbolAddress((void**)&p_a, g_a);
    cudaGetSymbolAddress((void**)&p_cc_h, g_cc_h);
    cudaGetSymbolAddress((void**)&p_nm_h, g_nm_h);
    cudaGetSymbolAddress((void**)&p_hd_h, g_hd_h);
    cudaGetSymbolAddress((void**)&p_wt_h, g_wt_h);
    cudaGetSymbolAddress((void**)&p_xnew, g_xnew);
    cudaGetSymbolAddress((void**)&p_splam, g_splam);

    cudaFuncSetAttribute(hgemm<1>, cudaFuncAttributeMaxDynamicSharedMemorySize, GEMM_SMEM);
    cudaFuncSetAttribute(hgemm<2>, cudaFuncAttributeMaxDynamicSharedMemorySize, GEMM_SMEM);
    cudaFuncSetAttribute(hgemm<3>, cudaFuncAttributeMaxDynamicSharedMemorySize, GEMM_SMEM);
    cudaFuncSetAttribute(hgemm<4>, cudaFuncAttributeMaxDynamicSharedMemorySize, GEMM_SMEM);

    // weight layout in g_wt_h (elements):
    //   [0,1M) gate  [1M,2M) a  [2M,4M) W_out^T  [4M,8M) W_ff1^T  [8M,12M) W_ff2^T
    const size_t OFF_GA = 0, OFF_OUT = (size_t)2 << 20,
                 OFF_FF1 = (size_t)4 << 20, OFF_FF2 = (size_t)8 << 20;
    transpose_all<<<12288, 256>>>(W_gate, W_a, W_out, W_ff1, W_ff2, p_wt_h);

    // pre-norm -> fp16
    rmsnorm_h<<<MM, 256>>>(x, pre_norm_w, p_xn_h);
    splam_kernel<<<4, 256>>>(lam);

    // fused gate+a GEMM (M=8192, N=2048, K=1024) with gating epilogue
    dim3 gGA(2048 / 128, MM / 128);
    hgemm<4><<<gGA, 256, GEMM_SMEM>>>(p_xn_h, p_wt_h + OFF_GA,
                                      p_a, 2048, 1024,
                                      nullptr, nullptr, nullptr, p_splam, nullptr, p_gate);

    // fused conv + u + scan chunk partials; combine; final scan
    gscan1_kernel<<<BB * DD * SCH / 256, 256>>>(conv_k, conv_b);
    scan_part2<<<BB * DD / 256, 256>>>();
    scan_part3<<<BB * DD * SCH / 256, 256>>>();

    // mixer GEMM (K=2048) + velocity + residual
    dim3 gD(1024 / 128, MM / 128);
    hgemm<1><<<gD, 256, GEMM_SMEM>>>(p_cc_h, p_wt_h + OFF_OUT,
                                     out_vel, 1024, 2048,
                                     b_out, velocity, x, log_beta, p_xnew, nullptr);

    // ffn norm
    rmsnorm_h<<<MM, 256>>>(p_xnew, ffn_norm_w, p_nm_h);

    // ff1 + gelu -> fp16 hidden (N=4096, K=1024)
    dim3 gF(4096 / 128, MM / 128);
    hgemm<2><<<gF, 256, GEMM_SMEM>>>(p_nm_h, p_wt_h + OFF_FF1,
                                     nullptr, 4096, 1024,
                                     b_ff1, nullptr, nullptr, nullptr, nullptr, p_hd_h);

    // ff2 + residual (K=4096) -> out1
    hgemm<3><<<gD, 256, GEMM_SMEM>>>(p_hd_h, p_wt_h + OFF_FF2,
                                     out1, 1024, 4096,
                                     b_ff2, p_xnew, nullptr, nullptr, nullptr, nullptr);
}